// round 4
// baseline (speedup 1.0000x reference)
#include <cuda_runtime.h>
#include <math.h>

#define NQ 256
#define MM 256
#define DDIM 256
#define EE 128
#define HH 4
#define HD_ 32
#define PP 64
#define NK (NQ*MM)        // 65536 keys
#define CHUNK 256
#define NCH (NK/CHUNK)    // 256 chunks per head

// ---------------- device scratch (static: no allocation allowed) ----------
__device__ float gPxT[NQ*EE];
__device__ float gPyT[MM*EE];
__device__ float gGxT[NQ*EE];
__device__ float gGyT[MM*EE];
__device__ float gCphiT[PP*EE];   // [p][e]
__device__ float gCgT[PP*EE];
__device__ float gdphi[EE];
__device__ float gdg[EE];
__device__ float gQ[HH*NQ*HD_];
__device__ float gK[NK*EE];       // 33.5 MB
__device__ float gV[NK*EE];       // 33.5 MB
__device__ float gPart[HH*NQ*NCH*34];  // m, l, acc[32] per (h,n,chunk)

// ---------------- 1: Px/Py/Gx/Gy = W[:, :256] @ src^T (stored transposed) --
#define WS_PITCH 260
__global__ void proj_kernel(const float* __restrict__ x,
                            const float* __restrict__ y,
                            const float* __restrict__ phi_w,
                            const float* __restrict__ g_w) {
    extern __shared__ float sm[];
    float* ws  = sm;                    // 128 x 260 (padded)
    float* row = sm + 128*WS_PITCH;     // 256
    int src  = blockIdx.x;              // 0:x 1:y
    int wi   = blockIdx.y;              // 0:phi 1:g
    int tile = blockIdx.z;              // 0..7 (32 rows each)
    const float* srcp = src ? y : x;
    const float* w    = wi ? g_w : phi_w;
    float* outT = src ? (wi ? gGyT : gPyT) : (wi ? gGxT : gPxT);
    int tid = threadIdx.x;              // 128
    for (int idx = tid; idx < 128*256; idx += 128) {
        int e = idx >> 8, dd = idx & 255;
        ws[e*WS_PITCH + dd] = w[e*384 + dd];
    }
    int e = tid;
    for (int rr = 0; rr < 32; ++rr) {
        int r = tile*32 + rr;
        __syncthreads();
        row[tid]       = srcp[r*256 + tid];
        row[tid + 128] = srcp[r*256 + tid + 128];
        __syncthreads();
        float acc = 0.f;
        const float4* wp = (const float4*)(ws + e*WS_PITCH);
        const float4* rp = (const float4*)row;
        #pragma unroll 8
        for (int u = 0; u < 64; ++u) {
            float4 a = wp[u]; float4 b = rp[u];
            acc += a.x*b.x + a.y*b.y + a.z*b.z + a.w*b.w;
        }
        outT[r*128 + e] = acc;
    }
}

// ---------------- 2: C = W[:,256:] @ k_w2 (stored [p][e]), d = W[:,256:]@k_b2
#define WE_PITCH 129
__global__ void cd_kernel(const float* __restrict__ phi_w,
                          const float* __restrict__ g_w,
                          const float* __restrict__ k_w2,
                          const float* __restrict__ k_b2) {
    extern __shared__ float sm[];
    float* we  = sm;                    // 128 x 129
    float* kw2 = sm + 128*WE_PITCH;     // 128 x 64
    int wi = blockIdx.x;
    const float* w = wi ? g_w : phi_w;
    float* CtT = wi ? gCgT : gCphiT;
    float* dv  = wi ? gdg  : gdphi;
    int tid = threadIdx.x;              // 256
    for (int idx = tid; idx < 128*128; idx += 256) {
        int e = idx >> 7, c = idx & 127;
        we[e*WE_PITCH + c] = w[e*384 + 256 + c];
    }
    for (int idx = tid; idx < 128*64; idx += 256) kw2[idx] = k_w2[idx];
    __syncthreads();
    int e  = tid & 127;
    int ph = tid >> 7;  // 0..1
    if (ph == 0) {
        float acc = 0.f;
        for (int c = 0; c < 128; ++c) acc += we[e*WE_PITCH + c]*k_b2[c];
        dv[e] = acc;
    }
    for (int p = ph*32; p < ph*32 + 32; ++p) {
        float acc = 0.f;
        #pragma unroll 8
        for (int c = 0; c < 128; ++c)
            acc += we[e*WE_PITCH + c] * kw2[c*64 + p];
        CtT[p*128 + e] = acc;
    }
}

// ---------------- 3: Q = scaling * theta_w @ [x ; qpe] ----------------------
__global__ void q_kernel(const float* __restrict__ x,
                         const float* __restrict__ x_pos,
                         const float* __restrict__ q_w1, const float* __restrict__ q_b1,
                         const float* __restrict__ q_w2, const float* __restrict__ q_b2,
                         const float* __restrict__ theta_w) {
    __shared__ __align__(16) float vec[384];
    __shared__ float hid[64];
    int n = blockIdx.x;
    int t = threadIdx.x;   // 128
    if (t < 64) {
        float r0 = x_pos[n*3], r1 = x_pos[n*3+1], r2 = x_pos[n*3+2];
        float h = q_w1[t*3]*r0 + q_w1[t*3+1]*r1 + q_w1[t*3+2]*r2 + q_b1[t];
        hid[t] = fmaxf(h, 0.f);
    }
    vec[t]       = x[n*256 + t];
    vec[t + 128] = x[n*256 + 128 + t];
    __syncthreads();
    float qpe = q_b2[t];
    #pragma unroll
    for (int p = 0; p < 64; ++p) qpe += q_w2[t*64 + p]*hid[p];
    vec[256 + t] = qpe;
    __syncthreads();
    float acc = 0.f;
    const float4* tw = (const float4*)(theta_w + t*384);
    const float4* vp = (const float4*)vec;
    #pragma unroll 8
    for (int u = 0; u < 96; ++u) {
        float4 a = tw[u]; float4 b = vp[u];
        acc += a.x*b.x + a.y*b.y + a.z*b.z + a.w*b.w;
    }
    acc *= 0.17677669529663687f;  // 1/sqrt(32)
    int h = t >> 5, d = t & 31;
    gQ[(h*NQ + n)*HD_ + d] = acc;
}

// ---------------- 4: generate K, V for all 65536 (n', m) pairs --------------
__global__ void genkv_kernel(const float* __restrict__ x_pos,
                             const float* __restrict__ y_pos,
                             const float* __restrict__ k_w1,
                             const float* __restrict__ k_b1) {
    extern __shared__ float sm[];
    float* Hs    = sm;                 // 128 pairs x 64
    float* Cp    = Hs + 128*64;        // 64 x 128
    float* Cg    = Cp + 64*128;        // 64 x 128
    float* baseK = Cg + 64*128;        // 128
    float* baseV = baseK + 128;        // 128
    float* yps   = baseV + 128;        // 128 x 3
    __shared__ float kw1s[64*3];
    __shared__ float kb1s[64];
    int tid = threadIdx.x;             // 256
    int np  = blockIdx.x >> 1;
    int m0  = (blockIdx.x & 1) * 128;
    for (int i = tid; i < 64*128; i += 256) { Cp[i] = gCphiT[i]; Cg[i] = gCgT[i]; }
    if (tid < 128) {
        baseK[tid] = gPxT[np*128 + tid] + gdphi[tid];
        baseV[tid] = gGxT[np*128 + tid] + gdg[tid];
    }
    for (int i = tid; i < 128*3; i += 256) yps[i] = y_pos[m0*3 + i];
    if (tid < 192) kw1s[tid] = k_w1[tid];
    if (tid < 64)  kb1s[tid] = k_b1[tid];
    __syncthreads();
    float xp0 = x_pos[np*3], xp1 = x_pos[np*3+1], xp2 = x_pos[np*3+2];
    for (int i = tid; i < 128*64; i += 256) {
        int pr = i >> 6, p = i & 63;
        float r0 = xp0 - yps[pr*3], r1 = xp1 - yps[pr*3+1], r2 = xp2 - yps[pr*3+2];
        float h = kw1s[p*3]*r0 + kw1s[p*3+1]*r1 + kw1s[p*3+2]*r2 + kb1s[p];
        Hs[pr*64 + p] = fmaxf(h, 0.f);
    }
    __syncthreads();
    int e  = (tid & 31) * 4;
    int pg = tid >> 5;  // 0..7, 16 pairs each
    float4 bK = *(const float4*)(baseK + e);
    float4 bV = *(const float4*)(baseV + e);
    for (int pr = pg*16; pr < pg*16 + 16; ++pr) {
        int m = m0 + pr;
        float4 py = *(const float4*)(gPyT + m*128 + e);
        float4 gy = *(const float4*)(gGyT + m*128 + e);
        float4 aK = make_float4(bK.x-py.x, bK.y-py.y, bK.z-py.z, bK.w-py.w);
        float4 aV = make_float4(bV.x-gy.x, bV.y-gy.y, bV.z-gy.z, bV.w-gy.w);
        const float* hrow = Hs + pr*64;
        #pragma unroll 16
        for (int p = 0; p < 64; ++p) {
            float hp = hrow[p];
            float4 c4 = *(const float4*)(Cp + p*128 + e);
            aK.x += c4.x*hp; aK.y += c4.y*hp; aK.z += c4.z*hp; aK.w += c4.w*hp;
            float4 g4 = *(const float4*)(Cg + p*128 + e);
            aV.x += g4.x*hp; aV.y += g4.y*hp; aV.z += g4.z*hp; aV.w += g4.w*hp;
        }
        int j = np*256 + m;
        *(float4*)(gK + j*128 + e) = aK;
        *(float4*)(gV + j*128 + e) = aV;
    }
}

// ---------------- 5: split-K flash attention partials -----------------------
__global__ void attn_kernel() {
    extern __shared__ float sm[];
    float* Kb = sm;                 // CHUNK x 32
    float* Vb = Kb + CHUNK*32;
    float* Qs = Vb + CHUNK*32;      // 256 x 32
    int h  = blockIdx.x >> 8;       // NCH = 256
    int ch = blockIdx.x & 255;
    int tid = threadIdx.x;          // 256
    int kbase = ch * CHUNK;
    int ebase = h * 32;
    for (int i = tid; i < CHUNK*8; i += 256) {
        int j = i >> 3, u = i & 7;
        *(float4*)(Kb + j*32 + u*4) = *(const float4*)(gK + (kbase+j)*128 + ebase + u*4);
        *(float4*)(Vb + j*32 + u*4) = *(const float4*)(gV + (kbase+j)*128 + ebase + u*4);
    }
    for (int i = tid; i < NQ*8; i += 256)
        *(float4*)(Qs + i*4) = *(const float4*)(gQ + h*NQ*HD_ + i*4);
    __syncthreads();
    int n = tid;
    float qv[32];
    #pragma unroll
    for (int u = 0; u < 8; ++u) {
        float4 q4 = *(const float4*)(Qs + n*32 + u*4);
        qv[u*4] = q4.x; qv[u*4+1] = q4.y; qv[u*4+2] = q4.z; qv[u*4+3] = q4.w;
    }
    float mmax = -1e30f, l = 0.f;
    float acc[32];
    #pragma unroll
    for (int d = 0; d < 32; ++d) acc[d] = 0.f;
    for (int j = 0; j < CHUNK; ++j) {
        const float4* kp = (const float4*)(Kb + j*32);
        float s0 = 0.f, s1 = 0.f, s2 = 0.f, s3 = 0.f;  // 4-way ILP dot
        #pragma unroll
        for (int u = 0; u < 8; ++u) {
            float4 k4 = kp[u];
            s0 += qv[u*4]*k4.x;   s1 += qv[u*4+1]*k4.y;
            s2 += qv[u*4+2]*k4.z; s3 += qv[u*4+3]*k4.w;
        }
        float s = (s0 + s1) + (s2 + s3);
        const float4* vp = (const float4*)(Vb + j*32);
        if (s <= mmax) {
            float pw = __expf(s - mmax);
            l += pw;
            #pragma unroll
            for (int u = 0; u < 8; ++u) {
                float4 v4 = vp[u];
                acc[u*4]   += pw*v4.x; acc[u*4+1] += pw*v4.y;
                acc[u*4+2] += pw*v4.z; acc[u*4+3] += pw*v4.w;
            }
        } else {
            float corr = __expf(mmax - s);
            mmax = s;
            l = l*corr + 1.f;
            #pragma unroll
            for (int u = 0; u < 8; ++u) {
                float4 v4 = vp[u];
                acc[u*4]   = acc[u*4]*corr   + v4.x;
                acc[u*4+1] = acc[u*4+1]*corr + v4.y;
                acc[u*4+2] = acc[u*4+2]*corr + v4.z;
                acc[u*4+3] = acc[u*4+3]*corr + v4.w;
            }
        }
    }
    float* out = gPart + ((h*NQ + n)*NCH + ch)*34;
    out[0] = mmax; out[1] = l;
    #pragma unroll
    for (int d = 0; d < 32; ++d) out[2+d] = acc[d];
}

// ---------------- 6: merge partials + out-proj + residual + LayerNorm -------
__global__ void merge_kernel(const float* __restrict__ x,
                             const float* __restrict__ out_w,
                             const float* __restrict__ ln_g,
                             const float* __restrict__ ln_b,
                             float* __restrict__ out) {
    __shared__ float wgt[HH][NCH];
    __shared__ float o_s[128];
    __shared__ float r_s[256];
    __shared__ float red[4];
    int n = blockIdx.x;
    int t = threadIdx.x;    // 128
    int h = t >> 5, d = t & 31;
    const float* base = gPart + (h*NQ + n)*NCH*34;
    // global max over chunks (one warp per head)
    float mloc = -1e30f;
    for (int c = d; c < NCH; c += 32) mloc = fmaxf(mloc, base[c*34]);
    #pragma unroll
    for (int o = 16; o > 0; o >>= 1)
        mloc = fmaxf(mloc, __shfl_xor_sync(0xffffffffu, mloc, o));
    float Mh = mloc;
    // chunk weights + total L
    float lloc = 0.f;
    for (int c = d; c < NCH; c += 32) {
        float w = __expf(base[c*34] - Mh);
        wgt[h][c] = w;
        lloc += base[c*34+1]*w;
    }
    #pragma unroll
    for (int o = 16; o > 0; o >>= 1) lloc += __shfl_xor_sync(0xffffffffu, lloc, o);
    // numerator (warp-private wgt, no sync needed yet)
    float onum = 0.f;
    for (int c = 0; c < NCH; ++c) onum += wgt[h][c]*base[c*34 + 2 + d];
    o_s[h*32 + d] = onum / lloc;
    __syncthreads();
    // out projection + residual
    for (int k = 0; k < 2; ++k) {
        int dd = t + k*128;
        float acc = x[n*256 + dd];
        const float4* wp = (const float4*)(out_w + dd*128);
        const float4* op = (const float4*)o_s;
        #pragma unroll 8
        for (int u = 0; u < 32; ++u) {
            float4 a = wp[u]; float4 b = op[u];
            acc += a.x*b.x + a.y*b.y + a.z*b.z + a.w*b.w;
        }
        r_s[dd] = acc;
    }
    __syncthreads();
    // LayerNorm
    float s = r_s[t] + r_s[t+128];
    #pragma unroll
    for (int o = 16; o > 0; o >>= 1) s += __shfl_xor_sync(0xffffffffu, s, o);
    if ((t & 31) == 0) red[t >> 5] = s;
    __syncthreads();
    float mu = (red[0] + red[1] + red[2] + red[3]) * (1.f/256.f);
    float d0 = r_s[t] - mu, d1 = r_s[t+128] - mu;
    float sq = d0*d0 + d1*d1;
    #pragma unroll
    for (int o = 16; o > 0; o >>= 1) sq += __shfl_xor_sync(0xffffffffu, sq, o);
    __syncthreads();
    if ((t & 31) == 0) red[t >> 5] = sq;
    __syncthreads();
    float var = (red[0] + red[1] + red[2] + red[3]) * (1.f/256.f);
    float rstd = rsqrtf(var + 1e-5f);
    out[n*256 + t]       = d0*rstd*ln_g[t]     + ln_b[t];
    out[n*256 + t + 128] = d1*rstd*ln_g[t+128] + ln_b[t+128];
}

// ---------------- launcher --------------------------------------------------
extern "C" void kernel_launch(void* const* d_in, const int* in_sizes, int n_in,
                              void* d_out, int out_size) {
    const float* x       = (const float*)d_in[0];
    const float* y       = (const float*)d_in[1];
    const float* x_pos   = (const float*)d_in[2];
    const float* y_pos   = (const float*)d_in[3];
    const float* theta_w = (const float*)d_in[4];
    const float* phi_w   = (const float*)d_in[5];
    const float* g_w     = (const float*)d_in[6];
    const float* q_w1    = (const float*)d_in[7];
    const float* q_b1    = (const float*)d_in[8];
    const float* q_w2    = (const float*)d_in[9];
    const float* q_b2    = (const float*)d_in[10];
    const float* k_w1    = (const float*)d_in[11];
    const float* k_b1    = (const float*)d_in[12];
    const float* k_w2    = (const float*)d_in[13];
    const float* k_b2    = (const float*)d_in[14];
    const float* out_w   = (const float*)d_in[15];
    const float* ln_g    = (const float*)d_in[16];
    const float* ln_b    = (const float*)d_in[17];
    float* out = (float*)d_out;

    size_t smem_proj  = (size_t)(128*WS_PITCH + 256) * sizeof(float);
    size_t smem_cd    = (size_t)(128*WE_PITCH + 128*64) * sizeof(float);
    size_t smem_genkv = (size_t)(128*64 + 64*128*2 + 128*2 + 128*3) * sizeof(float);
    size_t smem_attn  = (size_t)(CHUNK*32*2 + NQ*32) * sizeof(float);
    cudaFuncSetAttribute(proj_kernel,  cudaFuncAttributeMaxDynamicSharedMemorySize, (int)smem_proj);
    cudaFuncSetAttribute(cd_kernel,    cudaFuncAttributeMaxDynamicSharedMemorySize, (int)smem_cd);
    cudaFuncSetAttribute(genkv_kernel, cudaFuncAttributeMaxDynamicSharedMemorySize, (int)smem_genkv);
    cudaFuncSetAttribute(attn_kernel,  cudaFuncAttributeMaxDynamicSharedMemorySize, (int)smem_attn);

    proj_kernel<<<dim3(2,2,8), 128, smem_proj>>>(x, y, phi_w, g_w);
    cd_kernel<<<2, 256, smem_cd>>>(phi_w, g_w, k_w2, k_b2);
    q_kernel<<<256, 128>>>(x, x_pos, q_w1, q_b1, q_w2, q_b2, theta_w);
    genkv_kernel<<<512, 256, smem_genkv>>>(x_pos, y_pos, k_w1, k_b1);
    attn_kernel<<<HH*NCH, 256, smem_attn>>>();
    merge_kernel<<<NQ, 128>>>(x, out_w, ln_g, ln_b, out);
}

// round 6
// speedup vs baseline: 2.9973x; 2.9973x over previous
#include <cuda_runtime.h>
#include <cuda_bf16.h>
#include <math.h>

#define NQ 256
#define MM 256
#define EE 128
#define HH 4
#define PP 64
#define NK (NQ*MM)        // 65536 keys
#define CHUNK 512
#define NCH (NK/CHUNK)    // 128 chunks per head

// ---------------- device scratch (static: no allocation allowed) ----------
__device__ float gPxT[NQ*EE];
__device__ float gPyT[MM*EE];
__device__ float gGxT[NQ*EE];
__device__ float gGyT[MM*EE];
__device__ float gdphi[EE];
__device__ float gdg[EE];
__device__ float gQ[HH*NQ*32];            // pre-scaled by 1/sqrt(32)*log2(e)
__device__ unsigned short gCphiB[EE*PP];  // bf16 [e][p]
__device__ unsigned short gCgB[EE*PP];    // bf16 [e][p]
__device__ unsigned short gKb[NK*EE];     // bf16 K, 16.8 MB
__device__ unsigned short gVb[NK*EE];     // bf16 V, 16.8 MB
__device__ float gPartO[(size_t)HH*NQ*NCH*32];  // 16.8 MB
__device__ float gPartL[HH*NQ*NCH];

// ---------------- mma helpers ----------------------------------------------
__device__ __forceinline__ unsigned pk(float lo, float hi) {
    unsigned d;
    asm("cvt.rn.bf16x2.f32 %0, %1, %2;" : "=r"(d) : "f"(hi), "f"(lo));
    return d;
}
__device__ __forceinline__ float ex2(float x) {
    float d;
    asm("ex2.approx.f32 %0, %1;" : "=f"(d) : "f"(x));
    return d;
}
__device__ __forceinline__ void mma16816(float* c, const unsigned* a, const unsigned* b) {
    asm volatile(
        "mma.sync.aligned.m16n8k16.row.col.f32.bf16.bf16.f32 "
        "{%0,%1,%2,%3},{%4,%5,%6,%7},{%8,%9},{%0,%1,%2,%3};"
        : "+f"(c[0]), "+f"(c[1]), "+f"(c[2]), "+f"(c[3])
        : "r"(a[0]), "r"(a[1]), "r"(a[2]), "r"(a[3]), "r"(b[0]), "r"(b[1]));
}

// ---------------- 1: Px/Py/Gx/Gy = W[:, :256] @ src^T (stored transposed) --
#define WS_PITCH 260
__global__ void proj_kernel(const float* __restrict__ x,
                            const float* __restrict__ y,
                            const float* __restrict__ phi_w,
                            const float* __restrict__ g_w) {
    extern __shared__ float sm[];
    float* ws  = sm;                    // 128 x 260 (padded)
    float* row = sm + 128*WS_PITCH;     // 256
    int src  = blockIdx.x;              // 0:x 1:y
    int wi   = blockIdx.y;              // 0:phi 1:g
    int tile = blockIdx.z;              // 0..7 (32 rows each)
    const float* srcp = src ? y : x;
    const float* w    = wi ? g_w : phi_w;
    float* outT = src ? (wi ? gGyT : gPyT) : (wi ? gGxT : gPxT);
    int tid = threadIdx.x;              // 128
    for (int idx = tid; idx < 128*256; idx += 128) {
        int e = idx >> 8, dd = idx & 255;
        ws[e*WS_PITCH + dd] = w[e*384 + dd];
    }
    int e = tid;
    for (int rr = 0; rr < 32; ++rr) {
        int r = tile*32 + rr;
        __syncthreads();
        row[tid]       = srcp[r*256 + tid];
        row[tid + 128] = srcp[r*256 + tid + 128];
        __syncthreads();
        float acc = 0.f;
        const float4* wp = (const float4*)(ws + e*WS_PITCH);
        const float4* rp = (const float4*)row;
        #pragma unroll 8
        for (int u = 0; u < 64; ++u) {
            float4 a = wp[u]; float4 b = rp[u];
            acc += a.x*b.x + a.y*b.y + a.z*b.z + a.w*b.w;
        }
        outT[r*128 + e] = acc;
    }
}

// ---------------- 2: C = W[:,256:] @ k_w2 (bf16, [e][p]), d = W[:,256:]@k_b2
#define WE_PITCH 129
__global__ void cd_kernel(const float* __restrict__ phi_w,
                          const float* __restrict__ g_w,
                          const float* __restrict__ k_w2,
                          const float* __restrict__ k_b2) {
    extern __shared__ float sm[];
    float* we  = sm;                    // 128 x 129
    float* kw2 = sm + 128*WE_PITCH;     // 128 x 64
    int wi = blockIdx.x;
    const float* w = wi ? g_w : phi_w;
    unsigned short* CtB = wi ? gCgB : gCphiB;
    float* dv  = wi ? gdg  : gdphi;
    int tid = threadIdx.x;              // 256
    for (int idx = tid; idx < 128*128; idx += 256) {
        int e = idx >> 7, c = idx & 127;
        we[e*WE_PITCH + c] = w[e*384 + 256 + c];
    }
    for (int idx = tid; idx < 128*64; idx += 256) kw2[idx] = k_w2[idx];
    __syncthreads();
    int e  = tid & 127;
    int ph = tid >> 7;  // 0..1
    if (ph == 0) {
        float acc = 0.f;
        for (int c = 0; c < 128; ++c) acc += we[e*WE_PITCH + c]*k_b2[c];
        dv[e] = acc;
    }
    for (int p = ph*32; p < ph*32 + 32; ++p) {
        float acc = 0.f;
        #pragma unroll 8
        for (int c = 0; c < 128; ++c)
            acc += we[e*WE_PITCH + c] * kw2[c*64 + p];
        __nv_bfloat16 b = __float2bfloat16(acc);
        CtB[e*64 + p] = *(unsigned short*)&b;
    }
}

// ---------------- 3: Q = scale * theta_w @ [x ; qpe] ------------------------
__global__ void q_kernel(const float* __restrict__ x,
                         const float* __restrict__ x_pos,
                         const float* __restrict__ q_w1, const float* __restrict__ q_b1,
                         const float* __restrict__ q_w2, const float* __restrict__ q_b2,
                         const float* __restrict__ theta_w) {
    __shared__ __align__(16) float vec[384];
    __shared__ float hid[64];
    int n = blockIdx.x;
    int t = threadIdx.x;   // 128
    if (t < 64) {
        float r0 = x_pos[n*3], r1 = x_pos[n*3+1], r2 = x_pos[n*3+2];
        float h = q_w1[t*3]*r0 + q_w1[t*3+1]*r1 + q_w1[t*3+2]*r2 + q_b1[t];
        hid[t] = fmaxf(h, 0.f);
    }
    vec[t]       = x[n*256 + t];
    vec[t + 128] = x[n*256 + 128 + t];
    __syncthreads();
    float qpe = q_b2[t];
    #pragma unroll
    for (int p = 0; p < 64; ++p) qpe += q_w2[t*64 + p]*hid[p];
    vec[256 + t] = qpe;
    __syncthreads();
    float acc = 0.f;
    const float4* tw = (const float4*)(theta_w + t*384);
    const float4* vp = (const float4*)vec;
    #pragma unroll 8
    for (int u = 0; u < 96; ++u) {
        float4 a = tw[u]; float4 b = vp[u];
        acc += a.x*b.x + a.y*b.y + a.z*b.z + a.w*b.w;
    }
    // 1/sqrt(32) * log2(e): fold softmax scale + exp2 conversion into Q
    acc *= 0.17677669529663687f * 1.4426950408889634f;
    int h = t >> 5, d = t & 31;
    gQ[(h*NQ + n)*32 + d] = acc;
}

// ---------------- 4: genkv via bf16 mma: K/V = H@C + base - Py/Gy -----------
// smem: H bf16 [128][72], Cphi bf16 [128][72], Cg bf16 [128][72],
//       baseK f32[128], baseV f32[128], yps f32[384]
#define GK_H_OFF   0
#define GK_CP_OFF  18432
#define GK_CG_OFF  36864
#define GK_BK_OFF  55296
#define GK_BV_OFF  55808
#define GK_YP_OFF  56320
#define GK_SMEM    57856

__global__ void __launch_bounds__(256) genkv_kernel(const float* __restrict__ x_pos,
                             const float* __restrict__ y_pos,
                             const float* __restrict__ k_w1,
                             const float* __restrict__ k_b1) {
    extern __shared__ char smc[];
    unsigned short* Hs = (unsigned short*)(smc + GK_H_OFF);
    float* baseK = (float*)(smc + GK_BK_OFF);
    float* baseV = (float*)(smc + GK_BV_OFF);
    float* yps   = (float*)(smc + GK_YP_OFF);
    __shared__ float kw1s[192], kb1s[64];
    int tid = threadIdx.x;              // 256
    int np = blockIdx.x >> 1;
    int mh = blockIdx.x & 1;
    // copy C matrices, pad rows 64 -> 72 bf16 (conflict-free B-frag loads)
    for (int i = tid; i < 128*32; i += 256) {
        int e = i >> 5, c = i & 31;
        ((unsigned*)(smc + GK_CP_OFF + e*144))[c] = ((const unsigned*)gCphiB)[e*32 + c];
        ((unsigned*)(smc + GK_CG_OFF + e*144))[c] = ((const unsigned*)gCgB)[e*32 + c];
    }
    if (tid < 128) {
        baseK[tid] = gPxT[np*128 + tid] + gdphi[tid];
        baseV[tid] = gGxT[np*128 + tid] + gdg[tid];
    }
    for (int i = tid; i < 384; i += 256) yps[i] = y_pos[mh*384 + i];
    if (tid < 192) kw1s[tid] = k_w1[tid];
    if (tid < 64)  kb1s[tid] = k_b1[tid];
    __syncthreads();
    float xp0 = x_pos[np*3], xp1 = x_pos[np*3+1], xp2 = x_pos[np*3+2];
    for (int i = tid; i < 128*64; i += 256) {
        int pr = i >> 6, p = i & 63;
        float r0 = xp0 - yps[pr*3], r1 = xp1 - yps[pr*3+1], r2 = xp2 - yps[pr*3+2];
        float h = fmaxf(kw1s[p*3]*r0 + kw1s[p*3+1]*r1 + kw1s[p*3+2]*r2 + kb1s[p], 0.f);
        __nv_bfloat16 hb = __float2bfloat16(h);
        Hs[pr*72 + p] = *(unsigned short*)&hb;
    }
    __syncthreads();
    int w = tid >> 5, lane = tid & 31, g = lane >> 2, q = lane & 3;
    int r0 = w*16;     // this warp's 16 pair-rows
    unsigned A[4][4];  // A frags for 4 k-tiles (p 0..63)
    #pragma unroll
    for (int kt = 0; kt < 4; ++kt) {
        int col = kt*16 + 2*q;
        A[kt][0] = *(const unsigned*)(Hs + (r0+g)*72 + col);
        A[kt][1] = *(const unsigned*)(Hs + (r0+g+8)*72 + col);
        A[kt][2] = *(const unsigned*)(Hs + (r0+g)*72 + col + 8);
        A[kt][3] = *(const unsigned*)(Hs + (r0+g+8)*72 + col + 8);
    }
    #pragma unroll
    for (int mat = 0; mat < 2; ++mat) {
        const unsigned short* Ct = (const unsigned short*)(smc + (mat ? GK_CG_OFF : GK_CP_OFF));
        const float* Py = mat ? gGyT : gPyT;
        const float* bs = mat ? baseV : baseK;
        unsigned short* outp = mat ? gVb : gKb;
        #pragma unroll
        for (int nt = 0; nt < 16; ++nt) {
            float c[4] = {0.f, 0.f, 0.f, 0.f};
            #pragma unroll
            for (int kt = 0; kt < 4; ++kt) {
                unsigned b[2];
                int col = kt*16 + 2*q;
                b[0] = *(const unsigned*)(Ct + (nt*8+g)*72 + col);
                b[1] = *(const unsigned*)(Ct + (nt*8+g)*72 + col + 8);
                mma16816(c, A[kt], b);
            }
            int e0 = nt*8 + 2*q;
            float b0 = bs[e0], b1 = bs[e0+1];
            int m  = mh*128 + r0 + g;
            float2 p0 = *(const float2*)(Py + m*128 + e0);
            *(unsigned*)(outp + (size_t)(np*256 + m)*128 + e0) = pk(c[0]+b0-p0.x, c[1]+b1-p0.y);
            int m2 = m + 8;
            float2 p1 = *(const float2*)(Py + m2*128 + e0);
            *(unsigned*)(outp + (size_t)(np*256 + m2)*128 + e0) = pk(c[2]+b0-p1.x, c[3]+b1-p1.y);
        }
    }
}

// ---------------- 5: bf16-mma flash attention partials (no-max softmax) -----
// smem: Ks bf16 [512][40] (padded rows), Vt bf16 [32][520] (padded rows)
#define AT_K_OFF 0
#define AT_V_OFF 40960
#define AT_SMEM  74240

__global__ void __launch_bounds__(256) attn_kernel() {
    extern __shared__ char smc[];
    unsigned short* Ks = (unsigned short*)(smc + AT_K_OFF);
    unsigned short* Vt = (unsigned short*)(smc + AT_V_OFF);
    int hh = blockIdx.x >> 7;     // NCH = 128
    int ch = blockIdx.x & 127;
    int tid = threadIdx.x;        // 256
    int kbase = ch*CHUNK;
    for (int rr = tid; rr < CHUNK; rr += 256) {
        const uint4* src = (const uint4*)(gKb + (size_t)(kbase+rr)*128 + hh*32);
        uint4* dst = (uint4*)(Ks + rr*40);
        dst[0] = src[0]; dst[1] = src[1]; dst[2] = src[2]; dst[3] = src[3];
        const uint4* vs = (const uint4*)(gVb + (size_t)(kbase+rr)*128 + hh*32);
        #pragma unroll
        for (int i = 0; i < 4; ++i) {
            uint4 u = vs[i];
            Vt[(i*8+0)*520 + rr] = (unsigned short)(u.x & 0xffff);
            Vt[(i*8+1)*520 + rr] = (unsigned short)(u.x >> 16);
            Vt[(i*8+2)*520 + rr] = (unsigned short)(u.y & 0xffff);
            Vt[(i*8+3)*520 + rr] = (unsigned short)(u.y >> 16);
            Vt[(i*8+4)*520 + rr] = (unsigned short)(u.z & 0xffff);
            Vt[(i*8+5)*520 + rr] = (unsigned short)(u.z >> 16);
            Vt[(i*8+6)*520 + rr] = (unsigned short)(u.w & 0xffff);
            Vt[(i*8+7)*520 + rr] = (unsigned short)(u.w >> 16);
        }
    }
    int w = tid >> 5, lane = tid & 31, g = lane >> 2, q = lane & 3;
    int qb = w*32;   // this warp's 32 queries
    unsigned Aq[2][2][4];  // [m-tile][k-tile(d)]
    const float* Qp = gQ + hh*NQ*32;
    #pragma unroll
    for (int mt = 0; mt < 2; ++mt)
      #pragma unroll
      for (int kt = 0; kt < 2; ++kt) {
        int rA = qb + mt*16 + g, rB = rA + 8;
        int c0 = kt*16 + 2*q, c1 = c0 + 8;
        float2 f;
        f = *(const float2*)(Qp + rA*32 + c0); Aq[mt][kt][0] = pk(f.x, f.y);
        f = *(const float2*)(Qp + rB*32 + c0); Aq[mt][kt][1] = pk(f.x, f.y);
        f = *(const float2*)(Qp + rA*32 + c1); Aq[mt][kt][2] = pk(f.x, f.y);
        f = *(const float2*)(Qp + rB*32 + c1); Aq[mt][kt][3] = pk(f.x, f.y);
      }
    __syncthreads();
    float O[2][4][4];
    #pragma unroll
    for (int a = 0; a < 2; ++a)
        #pragma unroll
        for (int b = 0; b < 4; ++b)
            #pragma unroll
            for (int cc = 0; cc < 4; ++cc) O[a][b][cc] = 0.f;
    float ls[2][2] = {{0.f, 0.f}, {0.f, 0.f}};
    for (int st = 0; st < CHUNK/16; ++st) {
        int key0 = st*16;
        unsigned Bk[2][2][2];
        #pragma unroll
        for (int ntk = 0; ntk < 2; ++ntk)
          #pragma unroll
          for (int kt = 0; kt < 2; ++kt) {
            const unsigned short* bp = Ks + (key0 + ntk*8 + g)*40 + kt*16 + 2*q;
            Bk[ntk][kt][0] = *(const unsigned*)(bp);
            Bk[ntk][kt][1] = *(const unsigned*)(bp + 8);
          }
        unsigned Bv[4][2];
        #pragma unroll
        for (int nt = 0; nt < 4; ++nt) {
            const unsigned short* bp = Vt + (nt*8+g)*520 + key0 + 2*q;
            Bv[nt][0] = *(const unsigned*)(bp);
            Bv[nt][1] = *(const unsigned*)(bp + 8);
        }
        #pragma unroll
        for (int mt = 0; mt < 2; ++mt) {
            float S0[4] = {0,0,0,0}, S1[4] = {0,0,0,0};
            mma16816(S0, Aq[mt][0], Bk[0][0]);
            mma16816(S0, Aq[mt][1], Bk[0][1]);
            mma16816(S1, Aq[mt][0], Bk[1][0]);
            mma16816(S1, Aq[mt][1], Bk[1][1]);
            float p0 = ex2(S0[0]), p1 = ex2(S0[1]), p2 = ex2(S0[2]), p3 = ex2(S0[3]);
            float p4 = ex2(S1[0]), p5 = ex2(S1[1]), p6 = ex2(S1[2]), p7 = ex2(S1[3]);
            ls[mt][0] += (p0 + p1) + (p4 + p5);
            ls[mt][1] += (p2 + p3) + (p6 + p7);
            unsigned P[4] = { pk(p0, p1), pk(p2, p3), pk(p4, p5), pk(p6, p7) };
            #pragma unroll
            for (int nt = 0; nt < 4; ++nt)
                mma16816(O[mt][nt], P, Bv[nt]);
        }
    }
    #pragma unroll
    for (int mt = 0; mt < 2; ++mt) {
        float l0 = ls[mt][0], l1 = ls[mt][1];
        l0 += __shfl_xor_sync(0xffffffffu, l0, 1);
        l0 += __shfl_xor_sync(0xffffffffu, l0, 2);
        l1 += __shfl_xor_sync(0xffffffffu, l1, 1);
        l1 += __shfl_xor_sync(0xffffffffu, l1, 2);
        int n0 = qb + mt*16 + g;
        if (q == 0) {
            gPartL[(hh*NQ + n0)*NCH + ch]   = l0;
            gPartL[(hh*NQ + n0+8)*NCH + ch] = l1;
        }
        #pragma unroll
        for (int nt = 0; nt < 4; ++nt) {
            float2 v;
            v.x = O[mt][nt][0]; v.y = O[mt][nt][1];
            *(float2*)(gPartO + ((size_t)(hh*NQ + n0)*NCH + ch)*32 + nt*8 + 2*q) = v;
            v.x = O[mt][nt][2]; v.y = O[mt][nt][3];
            *(float2*)(gPartO + ((size_t)(hh*NQ + n0+8)*NCH + ch)*32 + nt*8 + 2*q) = v;
        }
    }
}

// ---------------- 6: merge partials + out-proj + residual + LayerNorm -------
__global__ void merge_kernel(const float* __restrict__ x,
                             const float* __restrict__ out_w,
                             const float* __restrict__ ln_g,
                             const float* __restrict__ ln_b,
                             float* __restrict__ out) {
    __shared__ float o_s[128];
    __shared__ float r_s[256];
    __shared__ float red[4];
    int n = blockIdx.x;
    int t = threadIdx.x;    // 128
    int h = t >> 5, d = t & 31;
    const float* po = gPartO + ((size_t)(h*NQ + n)*NCH)*32 + d;
    float acc = 0.f;
    #pragma unroll 8
    for (int c = 0; c < NCH; ++c) acc += po[c*32];
    const float* pl = gPartL + (h*NQ + n)*NCH;
    float ll = 0.f;
    for (int c = d; c < NCH; c += 32) ll += pl[c];
    #pragma unroll
    for (int o = 16; o > 0; o >>= 1) ll += __shfl_xor_sync(0xffffffffu, ll, o);
    o_s[h*32 + d] = acc / ll;
    __syncthreads();
    // out projection + residual
    for (int k = 0; k < 2; ++k) {
        int dd = t + k*128;
        float a = x[n*256 + dd];
        const float4* wp = (const float4*)(out_w + dd*128);
        const float4* op = (const float4*)o_s;
        #pragma unroll 8
        for (int u = 0; u < 32; ++u) {
            float4 aa = wp[u]; float4 bb = op[u];
            a += aa.x*bb.x + aa.y*bb.y + aa.z*bb.z + aa.w*bb.w;
        }
        r_s[dd] = a;
    }
    __syncthreads();
    // LayerNorm
    float s = r_s[t] + r_s[t+128];
    #pragma unroll
    for (int o = 16; o > 0; o >>= 1) s += __shfl_xor_sync(0xffffffffu, s, o);
    if ((t & 31) == 0) red[t >> 5] = s;
    __syncthreads();
    float mu = (red[0] + red[1] + red[2] + red[3]) * (1.f/256.f);
    float d0 = r_s[t] - mu, d1 = r_s[t+128] - mu;
    float sq = d0*d0 + d1*d1;
    #pragma unroll
    for (int o = 16; o > 0; o >>= 1) sq += __shfl_xor_sync(0xffffffffu, sq, o);
    __syncthreads();
    if ((t & 31) == 0) red[t >> 5] = sq;
    __syncthreads();
    float var = (red[0] + red[1] + red[2] + red[3]) * (1.f/256.f);
    float rstd = rsqrtf(var + 1e-5f);
    out[n*256 + t]       = d0*rstd*ln_g[t]     + ln_b[t];
    out[n*256 + t + 128] = d1*rstd*ln_g[t+128] + ln_b[t+128];
}

// ---------------- launcher --------------------------------------------------
extern "C" void kernel_launch(void* const* d_in, const int* in_sizes, int n_in,
                              void* d_out, int out_size) {
    const float* x       = (const float*)d_in[0];
    const float* y       = (const float*)d_in[1];
    const float* x_pos   = (const float*)d_in[2];
    const float* y_pos   = (const float*)d_in[3];
    const float* theta_w = (const float*)d_in[4];
    const float* phi_w   = (const float*)d_in[5];
    const float* g_w     = (const float*)d_in[6];
    const float* q_w1    = (const float*)d_in[7];
    const float* q_b1    = (const float*)d_in[8];
    const float* q_w2    = (const float*)d_in[9];
    const float* q_b2    = (const float*)d_in[10];
    const float* k_w1    = (const float*)d_in[11];
    const float* k_b1    = (const float*)d_in[12];
    const float* k_w2    = (const float*)d_in[13];
    const float* k_b2    = (const float*)d_in[14];
    const float* out_w   = (const float*)d_in[15];
    const float* ln_g    = (const float*)d_in[16];
    const float* ln_b    = (const float*)d_in[17];
    float* out = (float*)d_out;

    size_t smem_proj = (size_t)(128*WS_PITCH + 256) * sizeof(float);
    size_t smem_cd   = (size_t)(128*WE_PITCH + 128*64) * sizeof(float);
    cudaFuncSetAttribute(proj_kernel,  cudaFuncAttributeMaxDynamicSharedMemorySize, (int)smem_proj);
    cudaFuncSetAttribute(cd_kernel,    cudaFuncAttributeMaxDynamicSharedMemorySize, (int)smem_cd);
    cudaFuncSetAttribute(genkv_kernel, cudaFuncAttributeMaxDynamicSharedMemorySize, GK_SMEM);
    cudaFuncSetAttribute(attn_kernel,  cudaFuncAttributeMaxDynamicSharedMemorySize, AT_SMEM);

    proj_kernel<<<dim3(2,2,8), 128, smem_proj>>>(x, y, phi_w, g_w);
    cd_kernel<<<2, 256, smem_cd>>>(phi_w, g_w, k_w2, k_b2);
    q_kernel<<<256, 128>>>(x, x_pos, q_w1, q_b1, q_w2, q_b2, theta_w);
    genkv_kernel<<<512, 256, GK_SMEM>>>(x_pos, y_pos, k_w1, k_b1);
    attn_kernel<<<HH*NCH, 256, AT_SMEM>>>();
    merge_kernel<<<NQ, 128>>>(x, out_w, ln_g, ln_b, out);
}

// round 7
// speedup vs baseline: 3.9478x; 1.3171x over previous
#include <cuda_runtime.h>
#include <cuda_bf16.h>
#include <math.h>

#define NQ 256
#define MM 256
#define EE 128
#define HH 4
#define PP 64
#define NK (NQ*MM)        // 65536 keys
#define CHUNK 256
#define NCH (NK/CHUNK)    // 256 chunks per head

// ---------------- device scratch (static: no allocation allowed) ----------
__device__ float gPxT[NQ*EE];
__device__ float gPyT[MM*EE];
__device__ float gGxT[NQ*EE];
__device__ float gGyT[MM*EE];
__device__ float gdphi[EE];
__device__ float gdg[EE];
__device__ float gQ[HH*NQ*32];            // pre-scaled by 1/sqrt(32)*log2(e)
__device__ unsigned short gCphiB[EE*PP];  // bf16 [e][p]
__device__ unsigned short gCgB[EE*PP];    // bf16 [e][p]
__device__ unsigned short gKb[NK*EE];     // bf16 K, 16.8 MB
__device__ unsigned short gVb[NK*EE];     // bf16 V, 16.8 MB
__device__ float gPartO[(size_t)HH*NQ*NCH*32];  // 33.5 MB
__device__ float gPartL[HH*NQ*NCH];

// ---------------- mma / ldmatrix helpers ------------------------------------
__device__ __forceinline__ unsigned pk(float lo, float hi) {
    unsigned d;
    asm("cvt.rn.bf16x2.f32 %0, %1, %2;" : "=r"(d) : "f"(hi), "f"(lo));
    return d;
}
__device__ __forceinline__ float ex2(float x) {
    float d;
    asm("ex2.approx.f32 %0, %1;" : "=f"(d) : "f"(x));
    return d;
}
__device__ __forceinline__ void mma16816(float* c, const unsigned* a, const unsigned* b) {
    asm volatile(
        "mma.sync.aligned.m16n8k16.row.col.f32.bf16.bf16.f32 "
        "{%0,%1,%2,%3},{%4,%5,%6,%7},{%8,%9},{%0,%1,%2,%3};"
        : "+f"(c[0]), "+f"(c[1]), "+f"(c[2]), "+f"(c[3])
        : "r"(a[0]), "r"(a[1]), "r"(a[2]), "r"(a[3]), "r"(b[0]), "r"(b[1]));
}
__device__ __forceinline__ void ldsm4(unsigned& x, unsigned& y, unsigned& z, unsigned& w,
                                      unsigned addr) {
    asm volatile("ldmatrix.sync.aligned.m8n8.x4.shared.b16 {%0,%1,%2,%3}, [%4];"
                 : "=r"(x), "=r"(y), "=r"(z), "=r"(w) : "r"(addr));
}
__device__ __forceinline__ void ldsm4t(unsigned& x, unsigned& y, unsigned& z, unsigned& w,
                                       unsigned addr) {
    asm volatile("ldmatrix.sync.aligned.m8n8.x4.trans.shared.b16 {%0,%1,%2,%3}, [%4];"
                 : "=r"(x), "=r"(y), "=r"(z), "=r"(w) : "r"(addr));
}

// ---------------- 1: Px/Py/Gx/Gy = W[:, :256] @ src^T (stored transposed) --
// float2, pitch 258 -> conflict-free LDS.64; 8 rows/block, grid (2,2,32)
#define WS_PITCH 258
__global__ void proj_kernel(const float* __restrict__ x,
                            const float* __restrict__ y,
                            const float* __restrict__ phi_w,
                            const float* __restrict__ g_w) {
    extern __shared__ float sm[];
    float* ws  = sm;                    // 128 x 258
    float* row = sm + 128*WS_PITCH;     // 256
    int src  = blockIdx.x;              // 0:x 1:y
    int wi   = blockIdx.y;              // 0:phi 1:g
    int tile = blockIdx.z;              // 0..31 (8 rows each)
    const float* srcp = src ? y : x;
    const float* w    = wi ? g_w : phi_w;
    float* outT = src ? (wi ? gGyT : gPyT) : (wi ? gGxT : gPxT);
    int tid = threadIdx.x;              // 128
    for (int idx = tid; idx < 128*256; idx += 128) {
        int e = idx >> 8, dd = idx & 255;
        ws[e*WS_PITCH + dd] = w[e*384 + dd];
    }
    int e = tid;
    for (int rr = 0; rr < 8; ++rr) {
        int r = tile*8 + rr;
        __syncthreads();
        row[tid]       = srcp[r*256 + tid];
        row[tid + 128] = srcp[r*256 + tid + 128];
        __syncthreads();
        float acc = 0.f;
        const float2* wp = (const float2*)(ws + e*WS_PITCH);
        const float2* rp = (const float2*)row;
        #pragma unroll 16
        for (int u = 0; u < 128; ++u) {
            float2 a = wp[u]; float2 b = rp[u];
            acc += a.x*b.x + a.y*b.y;
        }
        outT[r*128 + e] = acc;
    }
}

// ---------------- 2: C = W[:,256:] @ k_w2 (bf16, [e][p]), d = W[:,256:]@k_b2
#define WE_PITCH 129
__global__ void cd_kernel(const float* __restrict__ phi_w,
                          const float* __restrict__ g_w,
                          const float* __restrict__ k_w2,
                          const float* __restrict__ k_b2) {
    extern __shared__ float sm[];
    float* we  = sm;                    // 128 x 129
    float* kw2 = sm + 128*WE_PITCH;     // 128 x 64
    int wi = blockIdx.x & 1;
    int pg = blockIdx.x >> 1;           // 0..7, 8 p's per block
    const float* w = wi ? g_w : phi_w;
    unsigned short* CtB = wi ? gCgB : gCphiB;
    float* dv  = wi ? gdg  : gdphi;
    int tid = threadIdx.x;              // 256
    for (int idx = tid; idx < 128*128; idx += 256) {
        int e = idx >> 7, c = idx & 127;
        we[e*WE_PITCH + c] = w[e*384 + 256 + c];
    }
    for (int idx = tid; idx < 128*64; idx += 256) kw2[idx] = k_w2[idx];
    __syncthreads();
    int e  = tid & 127;
    int ph = tid >> 7;  // 0..1
    if (pg == 0 && ph == 0) {
        float acc = 0.f;
        for (int c = 0; c < 128; ++c) acc += we[e*WE_PITCH + c]*k_b2[c];
        dv[e] = acc;
    }
    for (int j = 0; j < 4; ++j) {
        int p = pg*8 + ph*4 + j;
        float acc = 0.f;
        #pragma unroll 8
        for (int c = 0; c < 128; ++c)
            acc += we[e*WE_PITCH + c] * kw2[c*64 + p];
        __nv_bfloat16 b = __float2bfloat16(acc);
        CtB[e*64 + p] = *(unsigned short*)&b;
    }
}

// ---------------- 3: Q = scale * theta_w @ [x ; qpe] ------------------------
__global__ void q_kernel(const float* __restrict__ x,
                         const float* __restrict__ x_pos,
                         const float* __restrict__ q_w1, const float* __restrict__ q_b1,
                         const float* __restrict__ q_w2, const float* __restrict__ q_b2,
                         const float* __restrict__ theta_w) {
    __shared__ __align__(16) float vec[384];
    __shared__ float hid[64];
    int n = blockIdx.x;
    int t = threadIdx.x;   // 128
    if (t < 64) {
        float r0 = x_pos[n*3], r1 = x_pos[n*3+1], r2 = x_pos[n*3+2];
        float h = q_w1[t*3]*r0 + q_w1[t*3+1]*r1 + q_w1[t*3+2]*r2 + q_b1[t];
        hid[t] = fmaxf(h, 0.f);
    }
    vec[t]       = x[n*256 + t];
    vec[t + 128] = x[n*256 + 128 + t];
    __syncthreads();
    float qpe = q_b2[t];
    #pragma unroll
    for (int p = 0; p < 64; ++p) qpe += q_w2[t*64 + p]*hid[p];
    vec[256 + t] = qpe;
    __syncthreads();
    float acc = 0.f;
    const float4* tw = (const float4*)(theta_w + t*384);
    const float4* vp = (const float4*)vec;
    #pragma unroll 8
    for (int u = 0; u < 96; ++u) {
        float4 a = tw[u]; float4 b = vp[u];
        acc += a.x*b.x + a.y*b.y + a.z*b.z + a.w*b.w;
    }
    acc *= 0.17677669529663687f * 1.4426950408889634f;  // 1/sqrt(32)*log2(e)
    int h = t >> 5, d = t & 31;
    gQ[(h*NQ + n)*32 + d] = acc;
}

// ---------------- 4: genkv via bf16 mma: K/V = H@C + base - Py/Gy -----------
#define GK_H_OFF   0
#define GK_CP_OFF  18432
#define GK_CG_OFF  36864
#define GK_BK_OFF  55296
#define GK_BV_OFF  55808
#define GK_YP_OFF  56320
#define GK_SMEM    57856

__global__ void __launch_bounds__(256, 3) genkv_kernel(
                             const float* __restrict__ x_pos,
                             const float* __restrict__ y_pos,
                             const float* __restrict__ k_w1,
                             const float* __restrict__ k_b1) {
    extern __shared__ char smc[];
    unsigned short* Hs = (unsigned short*)(smc + GK_H_OFF);
    float* baseK = (float*)(smc + GK_BK_OFF);
    float* baseV = (float*)(smc + GK_BV_OFF);
    float* yps   = (float*)(smc + GK_YP_OFF);
    __shared__ float kw1s[192], kb1s[64];
    int tid = threadIdx.x;              // 256
    int np = blockIdx.x >> 1;
    int mh = blockIdx.x & 1;
    for (int i = tid; i < 128*32; i += 256) {
        int e = i >> 5, c = i & 31;
        ((unsigned*)(smc + GK_CP_OFF + e*144))[c] = ((const unsigned*)gCphiB)[e*32 + c];
        ((unsigned*)(smc + GK_CG_OFF + e*144))[c] = ((const unsigned*)gCgB)[e*32 + c];
    }
    if (tid < 128) {
        baseK[tid] = gPxT[np*128 + tid] + gdphi[tid];
        baseV[tid] = gGxT[np*128 + tid] + gdg[tid];
    }
    for (int i = tid; i < 384; i += 256) yps[i] = y_pos[mh*384 + i];
    if (tid < 192) kw1s[tid] = k_w1[tid];
    if (tid < 64)  kb1s[tid] = k_b1[tid];
    __syncthreads();
    float xp0 = x_pos[np*3], xp1 = x_pos[np*3+1], xp2 = x_pos[np*3+2];
    for (int i = tid; i < 128*64; i += 256) {
        int pr = i >> 6, p = i & 63;
        float r0 = xp0 - yps[pr*3], r1 = xp1 - yps[pr*3+1], r2 = xp2 - yps[pr*3+2];
        float h = fmaxf(kw1s[p*3]*r0 + kw1s[p*3+1]*r1 + kw1s[p*3+2]*r2 + kb1s[p], 0.f);
        __nv_bfloat16 hb = __float2bfloat16(h);
        Hs[pr*72 + p] = *(unsigned short*)&hb;
    }
    __syncthreads();
    int w = tid >> 5, lane = tid & 31, g = lane >> 2, q = lane & 3;
    int r0 = w*16;
    // A frags via ldmatrix.x4 (one per kt)
    unsigned A[4][4];
    {
        int arow = r0 + (lane & 7) + ((lane >> 3) & 1)*8;
        int acol = ((lane >> 4) & 1)*8;
        unsigned hbase = (unsigned)__cvta_generic_to_shared(Hs);
        #pragma unroll
        for (int kt = 0; kt < 4; ++kt)
            ldsm4(A[kt][0], A[kt][1], A[kt][2], A[kt][3],
                  hbase + (unsigned)((arow*72 + kt*16 + acol)*2));
    }
    unsigned cpb = (unsigned)__cvta_generic_to_shared(smc + GK_CP_OFF);
    unsigned cgb = (unsigned)__cvta_generic_to_shared(smc + GK_CG_OFF);
    int brow = lane & 7;
    int bcol = (lane >> 3)*8;
    int m  = mh*128 + r0 + g;
    int m2 = m + 8;
    size_t obase  = (size_t)(np*256 + m)*128;
    size_t obase2 = (size_t)(np*256 + m2)*128;
    // prefetch Py/Gy for nt=0
    float2 pK0 = *(const float2*)(gPyT + m*128  + 2*q);
    float2 pK1 = *(const float2*)(gPyT + m2*128 + 2*q);
    float2 pV0 = *(const float2*)(gGyT + m*128  + 2*q);
    float2 pV1 = *(const float2*)(gGyT + m2*128 + 2*q);
    #pragma unroll
    for (int nt = 0; nt < 16; ++nt) {
        unsigned off1 = (unsigned)(((nt*8 + brow)*72 + bcol)*2);
        unsigned bP[4][2], bG[4][2];
        ldsm4(bP[0][0], bP[0][1], bP[1][0], bP[1][1], cpb + off1);
        ldsm4(bP[2][0], bP[2][1], bP[3][0], bP[3][1], cpb + off1 + 64);
        ldsm4(bG[0][0], bG[0][1], bG[1][0], bG[1][1], cgb + off1);
        ldsm4(bG[2][0], bG[2][1], bG[3][0], bG[3][1], cgb + off1 + 64);
        float cK[4] = {0.f,0.f,0.f,0.f}, cV[4] = {0.f,0.f,0.f,0.f};
        #pragma unroll
        for (int kt = 0; kt < 4; ++kt) {
            mma16816(cK, A[kt], bP[kt]);
            mma16816(cV, A[kt], bG[kt]);
        }
        int e0 = nt*8 + 2*q;
        float2 cuK0 = pK0, cuK1 = pK1, cuV0 = pV0, cuV1 = pV1;
        if (nt < 15) {
            int e1 = e0 + 8;
            pK0 = *(const float2*)(gPyT + m*128  + e1);
            pK1 = *(const float2*)(gPyT + m2*128 + e1);
            pV0 = *(const float2*)(gGyT + m*128  + e1);
            pV1 = *(const float2*)(gGyT + m2*128 + e1);
        }
        float2 bk = *(const float2*)(baseK + e0);
        float2 bv = *(const float2*)(baseV + e0);
        *(unsigned*)(gKb + obase  + e0) = pk(cK[0]+bk.x-cuK0.x, cK[1]+bk.y-cuK0.y);
        *(unsigned*)(gKb + obase2 + e0) = pk(cK[2]+bk.x-cuK1.x, cK[3]+bk.y-cuK1.y);
        *(unsigned*)(gVb + obase  + e0) = pk(cV[0]+bv.x-cuV0.x, cV[1]+bv.y-cuV0.y);
        *(unsigned*)(gVb + obase2 + e0) = pk(cV[2]+bv.x-cuV1.x, cV[3]+bv.y-cuV1.y);
    }
}

// ---------------- 5: bf16-mma flash attention partials (no-max softmax) -----
// smem: Ks bf16 [256][40], Vs bf16 [256][40] (both row-major by key)
#define AT_K_OFF 0
#define AT_V_OFF 20480
#define AT_SMEM  40960

__global__ void __launch_bounds__(256, 2) attn_kernel() {
    extern __shared__ char smc[];
    unsigned short* Ks = (unsigned short*)(smc + AT_K_OFF);
    unsigned short* Vs = (unsigned short*)(smc + AT_V_OFF);
    int hh = blockIdx.x >> 8;     // NCH = 256
    int ch = blockIdx.x & 255;
    int tid = threadIdx.x;        // 256
    int kbase = ch*CHUNK;
    {
        int rr = tid;  // one row per thread
        const uint4* ks = (const uint4*)(gKb + (size_t)(kbase+rr)*128 + hh*32);
        const uint4* vs = (const uint4*)(gVb + (size_t)(kbase+rr)*128 + hh*32);
        uint4* kd = (uint4*)(Ks + rr*40);
        uint4* vd = (uint4*)(Vs + rr*40);
        #pragma unroll
        for (int i = 0; i < 4; ++i) { kd[i] = ks[i]; vd[i] = vs[i]; }
    }
    int w = tid >> 5, lane = tid & 31, g = lane >> 2, q = lane & 3;
    int qb = w*32;
    unsigned Aq[2][2][4];
    const float* Qp = gQ + hh*NQ*32;
    #pragma unroll
    for (int mt = 0; mt < 2; ++mt)
      #pragma unroll
      for (int kt = 0; kt < 2; ++kt) {
        int rA = qb + mt*16 + g, rB = rA + 8;
        int c0 = kt*16 + 2*q, c1 = c0 + 8;
        float2 f;
        f = *(const float2*)(Qp + rA*32 + c0); Aq[mt][kt][0] = pk(f.x, f.y);
        f = *(const float2*)(Qp + rB*32 + c0); Aq[mt][kt][1] = pk(f.x, f.y);
        f = *(const float2*)(Qp + rA*32 + c1); Aq[mt][kt][2] = pk(f.x, f.y);
        f = *(const float2*)(Qp + rB*32 + c1); Aq[mt][kt][3] = pk(f.x, f.y);
      }
    __syncthreads();
    unsigned ksb = (unsigned)__cvta_generic_to_shared(Ks);
    unsigned vsb = (unsigned)__cvta_generic_to_shared(Vs);
    int kRow = (lane & 7) + ((lane >> 4) & 1)*8;
    int kCol = ((lane >> 3) & 1)*8;
    int vRow = (lane & 7) + ((lane >> 3) & 1)*8;
    int vCol = ((lane >> 4) & 1)*8;
    float O[2][4][4];
    #pragma unroll
    for (int a = 0; a < 2; ++a)
        #pragma unroll
        for (int b = 0; b < 4; ++b)
            #pragma unroll
            for (int cc = 0; cc < 4; ++cc) O[a][b][cc] = 0.f;
    float ls[2][2] = {{0.f, 0.f}, {0.f, 0.f}};
    #pragma unroll 4
    for (int st = 0; st < CHUNK/16; ++st) {
        int key0 = st*16;
        unsigned Bk[2][2][2];  // [ntk][kt][reg]
        unsigned ak = ksb + (unsigned)(((key0 + kRow)*40 + kCol)*2);
        ldsm4(Bk[0][0][0], Bk[0][0][1], Bk[1][0][0], Bk[1][0][1], ak);
        ldsm4(Bk[0][1][0], Bk[0][1][1], Bk[1][1][0], Bk[1][1][1], ak + 32);
        unsigned Bv[4][2];
        unsigned av = vsb + (unsigned)(((key0 + vRow)*40 + vCol)*2);
        ldsm4t(Bv[0][0], Bv[0][1], Bv[1][0], Bv[1][1], av);
        ldsm4t(Bv[2][0], Bv[2][1], Bv[3][0], Bv[3][1], av + 32);
        #pragma unroll
        for (int mt = 0; mt < 2; ++mt) {
            float S0[4] = {0,0,0,0}, S1[4] = {0,0,0,0};
            mma16816(S0, Aq[mt][0], Bk[0][0]);
            mma16816(S1, Aq[mt][0], Bk[1][0]);
            mma16816(S0, Aq[mt][1], Bk[0][1]);
            mma16816(S1, Aq[mt][1], Bk[1][1]);
            float p0 = ex2(S0[0]), p1 = ex2(S0[1]), p2 = ex2(S0[2]), p3 = ex2(S0[3]);
            float p4 = ex2(S1[0]), p5 = ex2(S1[1]), p6 = ex2(S1[2]), p7 = ex2(S1[3]);
            ls[mt][0] += (p0 + p1) + (p4 + p5);
            ls[mt][1] += (p2 + p3) + (p6 + p7);
            unsigned P[4] = { pk(p0, p1), pk(p2, p3), pk(p4, p5), pk(p6, p7) };
            #pragma unroll
            for (int nt = 0; nt < 4; ++nt)
                mma16816(O[mt][nt], P, Bv[nt]);
        }
    }
    #pragma unroll
    for (int mt = 0; mt < 2; ++mt) {
        float l0 = ls[mt][0], l1 = ls[mt][1];
        l0 += __shfl_xor_sync(0xffffffffu, l0, 1);
        l0 += __shfl_xor_sync(0xffffffffu, l0, 2);
        l1 += __shfl_xor_sync(0xffffffffu, l1, 1);
        l1 += __shfl_xor_sync(0xffffffffu, l1, 2);
        int n0 = qb + mt*16 + g;
        if (q == 0) {
            gPartL[(hh*NQ + n0)*NCH + ch]   = l0;
            gPartL[(hh*NQ + n0+8)*NCH + ch] = l1;
        }
        #pragma unroll
        for (int nt = 0; nt < 4; ++nt) {
            float2 v;
            v.x = O[mt][nt][0]; v.y = O[mt][nt][1];
            *(float2*)(gPartO + ((size_t)(hh*NQ + n0)*NCH + ch)*32 + nt*8 + 2*q) = v;
            v.x = O[mt][nt][2]; v.y = O[mt][nt][3];
            *(float2*)(gPartO + ((size_t)(hh*NQ + n0+8)*NCH + ch)*32 + nt*8 + 2*q) = v;
        }
    }
}

// ---------------- 6: merge partials + out-proj + residual + LayerNorm -------
__global__ void merge_kernel(const float* __restrict__ x,
                             const float* __restrict__ out_w,
                             const float* __restrict__ ln_g,
                             const float* __restrict__ ln_b,
                             float* __restrict__ out) {
    __shared__ float o_s[128];
    __shared__ float r_s[256];
    __shared__ float red[4];
    int n = blockIdx.x;
    int t = threadIdx.x;    // 128
    int h = t >> 5, d = t & 31;
    const float* po = gPartO + ((size_t)(h*NQ + n)*NCH)*32 + d;
    float acc = 0.f;
    #pragma unroll 8
    for (int c = 0; c < NCH; ++c) acc += po[c*32];
    const float* pl = gPartL + (h*NQ + n)*NCH;
    float ll = 0.f;
    for (int c = d; c < NCH; c += 32) ll += pl[c];
    #pragma unroll
    for (int o = 16; o > 0; o >>= 1) ll += __shfl_xor_sync(0xffffffffu, ll, o);
    o_s[h*32 + d] = acc / ll;
    __syncthreads();
    for (int k = 0; k < 2; ++k) {
        int dd = t + k*128;
        float a = x[n*256 + dd];
        const float4* wp = (const float4*)(out_w + dd*128);
        const float4* op = (const float4*)o_s;
        #pragma unroll 8
        for (int u = 0; u < 32; ++u) {
            float4 aa = wp[u]; float4 bb = op[u];
            a += aa.x*bb.x + aa.y*bb.y + aa.z*bb.z + aa.w*bb.w;
        }
        r_s[dd] = a;
    }
    __syncthreads();
    float s = r_s[t] + r_s[t+128];
    #pragma unroll
    for (int o = 16; o > 0; o >>= 1) s += __shfl_xor_sync(0xffffffffu, s, o);
    if ((t & 31) == 0) red[t >> 5] = s;
    __syncthreads();
    float mu = (red[0] + red[1] + red[2] + red[3]) * (1.f/256.f);
    float d0 = r_s[t] - mu, d1 = r_s[t+128] - mu;
    float sq = d0*d0 + d1*d1;
    #pragma unroll
    for (int o = 16; o > 0; o >>= 1) sq += __shfl_xor_sync(0xffffffffu, sq, o);
    __syncthreads();
    if ((t & 31) == 0) red[t >> 5] = sq;
    __syncthreads();
    float var = (red[0] + red[1] + red[2] + red[3]) * (1.f/256.f);
    float rstd = rsqrtf(var + 1e-5f);
    out[n*256 + t]       = d0*rstd*ln_g[t]     + ln_b[t];
    out[n*256 + t + 128] = d1*rstd*ln_g[t+128] + ln_b[t+128];
}

// ---------------- launcher --------------------------------------------------
extern "C" void kernel_launch(void* const* d_in, const int* in_sizes, int n_in,
                              void* d_out, int out_size) {
    const float* x       = (const float*)d_in[0];
    const float* y       = (const float*)d_in[1];
    const float* x_pos   = (const float*)d_in[2];
    const float* y_pos   = (const float*)d_in[3];
    const float* theta_w = (const float*)d_in[4];
    const float* phi_w   = (const float*)d_in[5];
    const float* g_w     = (const float*)d_in[6];
    const float* q_w1    = (const float*)d_in[7];
    const float* q_b1    = (const float*)d_in[8];
    const float* q_w2    = (const float*)d_in[9];
    const float* q_b2    = (const float*)d_in[10];
    const float* k_w1    = (const float*)d_in[11];
    const float* k_b1    = (const float*)d_in[12];
    const float* k_w2    = (const float*)d_in[13];
    const float* k_b2    = (const float*)d_in[14];
    const float* out_w   = (const float*)d_in[15];
    const float* ln_g    = (const float*)d_in[16];
    const float* ln_b    = (const float*)d_in[17];
    float* out = (float*)d_out;

    size_t smem_proj = (size_t)(128*WS_PITCH + 256) * sizeof(float);
    size_t smem_cd   = (size_t)(128*WE_PITCH + 128*64) * sizeof(float);
    cudaFuncSetAttribute(proj_kernel,  cudaFuncAttributeMaxDynamicSharedMemorySize, (int)smem_proj);
    cudaFuncSetAttribute(cd_kernel,    cudaFuncAttributeMaxDynamicSharedMemorySize, (int)smem_cd);
    cudaFuncSetAttribute(genkv_kernel, cudaFuncAttributeMaxDynamicSharedMemorySize, GK_SMEM);
    cudaFuncSetAttribute(attn_kernel,  cudaFuncAttributeMaxDynamicSharedMemorySize, AT_SMEM);

    proj_kernel<<<dim3(2,2,32), 128, smem_proj>>>(x, y, phi_w, g_w);
    cd_kernel<<<16, 256, smem_cd>>>(phi_w, g_w, k_w2, k_b2);
    q_kernel<<<256, 128>>>(x, x_pos, q_w1, q_b1, q_w2, q_b2, theta_w);
    genkv_kernel<<<512, 256, GK_SMEM>>>(x_pos, y_pos, k_w1, k_b1);
    attn_kernel<<<HH*NCH, 256, AT_SMEM>>>();
    merge_kernel<<<NQ, 128>>>(x, out_w, ln_g, ln_b, out);
}

// round 8
// speedup vs baseline: 4.9593x; 1.2562x over previous
#include <cuda_runtime.h>
#include <cuda_bf16.h>
#include <math.h>

#define NQ 256
#define MM 256
#define EE 128
#define HH 4
#define PP 64
#define NK (NQ*MM)        // 65536 keys
#define CHUNK 256
#define NCH (NK/CHUNK)    // 256 chunks per head (= one np per chunk)

// ---------------- device scratch (static: no allocation allowed) ----------
__device__ float gPxT[NQ*EE];
__device__ float gPyT[MM*EE];
__device__ float gGxT[NQ*EE];
__device__ float gGyT[MM*EE];
__device__ float gdphi[EE];
__device__ float gdg[EE];
__device__ float gQ[HH*NQ*32];            // pre-scaled by 1/sqrt(32)*log2(e)
__device__ unsigned short gCphiB[EE*PP];  // bf16 [e][p]
__device__ unsigned short gCgB[EE*PP];    // bf16 [e][p]
__device__ float gPartO[(size_t)HH*NQ*NCH*32];  // 33.5 MB
__device__ float gPartL[HH*NQ*NCH];

// ---------------- mma / ldmatrix helpers ------------------------------------
__device__ __forceinline__ unsigned pk(float lo, float hi) {
    unsigned d;
    asm("cvt.rn.bf16x2.f32 %0, %1, %2;" : "=r"(d) : "f"(hi), "f"(lo));
    return d;
}
__device__ __forceinline__ float ex2(float x) {
    float d;
    asm("ex2.approx.f32 %0, %1;" : "=f"(d) : "f"(x));
    return d;
}
__device__ __forceinline__ void mma16816(float* c, const unsigned* a, const unsigned* b) {
    asm volatile(
        "mma.sync.aligned.m16n8k16.row.col.f32.bf16.bf16.f32 "
        "{%0,%1,%2,%3},{%4,%5,%6,%7},{%8,%9},{%0,%1,%2,%3};"
        : "+f"(c[0]), "+f"(c[1]), "+f"(c[2]), "+f"(c[3])
        : "r"(a[0]), "r"(a[1]), "r"(a[2]), "r"(a[3]), "r"(b[0]), "r"(b[1]));
}
__device__ __forceinline__ void ldsm4(unsigned& x, unsigned& y, unsigned& z, unsigned& w,
                                      unsigned addr) {
    asm volatile("ldmatrix.sync.aligned.m8n8.x4.shared.b16 {%0,%1,%2,%3}, [%4];"
                 : "=r"(x), "=r"(y), "=r"(z), "=r"(w) : "r"(addr));
}
__device__ __forceinline__ void ldsm4t(unsigned& x, unsigned& y, unsigned& z, unsigned& w,
                                       unsigned addr) {
    asm volatile("ldmatrix.sync.aligned.m8n8.x4.trans.shared.b16 {%0,%1,%2,%3}, [%4];"
                 : "=r"(x), "=r"(y), "=r"(z), "=r"(w) : "r"(addr));
}

// ---------------- 1: Px/Py/Gx/Gy = W[:, :256] @ src^T (stored transposed) --
#define WS_PITCH 258
__global__ void proj_kernel(const float* __restrict__ x,
                            const float* __restrict__ y,
                            const float* __restrict__ phi_w,
                            const float* __restrict__ g_w) {
    extern __shared__ float sm[];
    float* ws  = sm;                    // 128 x 258
    float* row = sm + 128*WS_PITCH;     // 256
    int src  = blockIdx.x;              // 0:x 1:y
    int wi   = blockIdx.y;              // 0:phi 1:g
    int tile = blockIdx.z;              // 0..31 (8 rows each)
    const float* srcp = src ? y : x;
    const float* w    = wi ? g_w : phi_w;
    float* outT = src ? (wi ? gGyT : gPyT) : (wi ? gGxT : gPxT);
    int tid = threadIdx.x;              // 128
    for (int idx = tid; idx < 128*256; idx += 128) {
        int e = idx >> 8, dd = idx & 255;
        ws[e*WS_PITCH + dd] = w[e*384 + dd];
    }
    int e = tid;
    for (int rr = 0; rr < 8; ++rr) {
        int r = tile*8 + rr;
        __syncthreads();
        row[tid]       = srcp[r*256 + tid];
        row[tid + 128] = srcp[r*256 + tid + 128];
        __syncthreads();
        float acc = 0.f;
        const float2* wp = (const float2*)(ws + e*WS_PITCH);
        const float2* rp = (const float2*)row;
        #pragma unroll 16
        for (int u = 0; u < 128; ++u) {
            float2 a = wp[u]; float2 b = rp[u];
            acc += a.x*b.x + a.y*b.y;
        }
        outT[r*128 + e] = acc;
    }
}

// ---------------- 2: C = W[:,256:] @ k_w2 (bf16, [e][p]), d = W[:,256:]@k_b2
#define WE_PITCH 129
__global__ void cd_kernel(const float* __restrict__ phi_w,
                          const float* __restrict__ g_w,
                          const float* __restrict__ k_w2,
                          const float* __restrict__ k_b2) {
    extern __shared__ float sm[];
    float* we  = sm;                    // 128 x 129
    float* kw2 = sm + 128*WE_PITCH;     // 128 x 64
    int wi = blockIdx.x & 1;
    int pg = blockIdx.x >> 1;           // 0..7, 8 p's per block
    const float* w = wi ? g_w : phi_w;
    unsigned short* CtB = wi ? gCgB : gCphiB;
    float* dv  = wi ? gdg  : gdphi;
    int tid = threadIdx.x;              // 256
    for (int idx = tid; idx < 128*128; idx += 256) {
        int e = idx >> 7, c = idx & 127;
        we[e*WE_PITCH + c] = w[e*384 + 256 + c];
    }
    for (int idx = tid; idx < 128*64; idx += 256) kw2[idx] = k_w2[idx];
    __syncthreads();
    int e  = tid & 127;
    int ph = tid >> 7;  // 0..1
    if (pg == 0 && ph == 0) {
        float acc = 0.f;
        for (int c = 0; c < 128; ++c) acc += we[e*WE_PITCH + c]*k_b2[c];
        dv[e] = acc;
    }
    for (int j = 0; j < 4; ++j) {
        int p = pg*8 + ph*4 + j;
        float acc = 0.f;
        #pragma unroll 8
        for (int c = 0; c < 128; ++c)
            acc += we[e*WE_PITCH + c] * kw2[c*64 + p];
        __nv_bfloat16 b = __float2bfloat16(acc);
        CtB[e*64 + p] = *(unsigned short*)&b;
    }
}

// ---------------- 3: Q = scale * theta_w @ [x ; qpe] ------------------------
__global__ void q_kernel(const float* __restrict__ x,
                         const float* __restrict__ x_pos,
                         const float* __restrict__ q_w1, const float* __restrict__ q_b1,
                         const float* __restrict__ q_w2, const float* __restrict__ q_b2,
                         const float* __restrict__ theta_w) {
    __shared__ __align__(16) float vec[384];
    __shared__ float hid[64];
    int n = blockIdx.x;
    int t = threadIdx.x;   // 128
    if (t < 64) {
        float r0 = x_pos[n*3], r1 = x_pos[n*3+1], r2 = x_pos[n*3+2];
        float h = q_w1[t*3]*r0 + q_w1[t*3+1]*r1 + q_w1[t*3+2]*r2 + q_b1[t];
        hid[t] = fmaxf(h, 0.f);
    }
    vec[t]       = x[n*256 + t];
    vec[t + 128] = x[n*256 + 128 + t];
    __syncthreads();
    float qpe = q_b2[t];
    #pragma unroll
    for (int p = 0; p < 64; ++p) qpe += q_w2[t*64 + p]*hid[p];
    vec[256 + t] = qpe;
    __syncthreads();
    float acc = 0.f;
    const float4* tw = (const float4*)(theta_w + t*384);
    const float4* vp = (const float4*)vec;
    #pragma unroll 8
    for (int u = 0; u < 96; ++u) {
        float4 a = tw[u]; float4 b = vp[u];
        acc += a.x*b.x + a.y*b.y + a.z*b.z + a.w*b.w;
    }
    acc *= 0.17677669529663687f * 1.4426950408889634f;  // 1/sqrt(32)*log2(e)
    int h = t >> 5, d = t & 31;
    gQ[(h*NQ + n)*32 + d] = acc;
}

// ---------------- 4: FUSED genkv + flash attention --------------------------
// One block per np: generate K/V[256 keys][128 e] into SMEM via bf16 mma,
// then run all 4 heads x 256 queries of attention against them.
// smem layout (bytes):
#define KPITCH 136
#define FZ_KS_OFF 0
#define FZ_VS_OFF 69632
#define FZ_H_OFF  139264
#define FZ_CP_OFF 176128
#define FZ_CG_OFF 194560
#define FZ_BK_OFF 212992
#define FZ_BV_OFF 213504
#define FZ_YP_OFF 214016
#define FZ_SMEM   217088

__global__ void __launch_bounds__(512, 1) fused_kernel(
        const float* __restrict__ x_pos, const float* __restrict__ y_pos,
        const float* __restrict__ k_w1, const float* __restrict__ k_b1) {
    extern __shared__ char smc[];
    unsigned short* Ks = (unsigned short*)(smc + FZ_KS_OFF);  // [256][136] bf16
    unsigned short* Vs = (unsigned short*)(smc + FZ_VS_OFF);  // [256][136] bf16
    unsigned short* Hs = (unsigned short*)(smc + FZ_H_OFF);   // [256][72]  bf16
    float* baseK = (float*)(smc + FZ_BK_OFF);
    float* baseV = (float*)(smc + FZ_BV_OFF);
    float* yps   = (float*)(smc + FZ_YP_OFF);                 // [256][3]
    __shared__ float kw1s[192], kb1s[64];
    int tid = threadIdx.x;   // 512
    int np  = blockIdx.x;    // 0..255

    // ---- phase A: stage constants + hidden MLP ----
    for (int i = tid; i < 128*32; i += 512) {
        int e = i >> 5, c = i & 31;
        ((unsigned*)(smc + FZ_CP_OFF + e*144))[c] = ((const unsigned*)gCphiB)[e*32 + c];
        ((unsigned*)(smc + FZ_CG_OFF + e*144))[c] = ((const unsigned*)gCgB)[e*32 + c];
    }
    if (tid < 128) {
        baseK[tid] = gPxT[np*128 + tid] + gdphi[tid];
        baseV[tid] = gGxT[np*128 + tid] + gdg[tid];
    }
    for (int i = tid; i < 768; i += 512) yps[i] = y_pos[i];
    if (tid < 192) kw1s[tid] = k_w1[tid];
    if (tid >= 256 && tid < 320) kb1s[tid-256] = k_b1[tid-256];
    __syncthreads();
    float xp0 = x_pos[np*3], xp1 = x_pos[np*3+1], xp2 = x_pos[np*3+2];
    for (int i = tid; i < 256*64; i += 512) {
        int pr = i >> 6, p = i & 63;
        float r0 = xp0 - yps[pr*3], r1 = xp1 - yps[pr*3+1], r2 = xp2 - yps[pr*3+2];
        float h = fmaxf(kw1s[p*3]*r0 + kw1s[p*3+1]*r1 + kw1s[p*3+2]*r2 + kb1s[p], 0.f);
        __nv_bfloat16 hb = __float2bfloat16(h);
        Hs[pr*72 + p] = *(unsigned short*)&hb;
    }
    __syncthreads();

    int w = tid >> 5, lane = tid & 31, g = lane >> 2, q = lane & 3;

    // ---- phase B: K/V = H@C + base - Py/Gy  -> SMEM (16 warps x 16 rows) ----
    {
        int r0 = w*16;
        unsigned A[4][4];
        int arow = r0 + (lane & 7) + ((lane >> 3) & 1)*8;
        int acol = ((lane >> 4) & 1)*8;
        unsigned hbase = (unsigned)__cvta_generic_to_shared(Hs);
        #pragma unroll
        for (int kt = 0; kt < 4; ++kt)
            ldsm4(A[kt][0], A[kt][1], A[kt][2], A[kt][3],
                  hbase + (unsigned)((arow*72 + kt*16 + acol)*2));
        unsigned cpb = (unsigned)__cvta_generic_to_shared(smc + FZ_CP_OFF);
        unsigned cgb = (unsigned)__cvta_generic_to_shared(smc + FZ_CG_OFF);
        int brow = lane & 7;
        int bcol = (lane >> 3)*8;
        int m  = r0 + g;
        int m2 = m + 8;
        // prefetch Py/Gy for nt=0
        float2 pK0 = *(const float2*)(gPyT + m*128  + 2*q);
        float2 pK1 = *(const float2*)(gPyT + m2*128 + 2*q);
        float2 pV0 = *(const float2*)(gGyT + m*128  + 2*q);
        float2 pV1 = *(const float2*)(gGyT + m2*128 + 2*q);
        #pragma unroll
        for (int nt = 0; nt < 16; ++nt) {
            unsigned off1 = (unsigned)(((nt*8 + brow)*72 + bcol)*2);
            unsigned bP[4][2], bG[4][2];
            ldsm4(bP[0][0], bP[0][1], bP[1][0], bP[1][1], cpb + off1);
            ldsm4(bP[2][0], bP[2][1], bP[3][0], bP[3][1], cpb + off1 + 64);
            ldsm4(bG[0][0], bG[0][1], bG[1][0], bG[1][1], cgb + off1);
            ldsm4(bG[2][0], bG[2][1], bG[3][0], bG[3][1], cgb + off1 + 64);
            float cK[4] = {0.f,0.f,0.f,0.f}, cV[4] = {0.f,0.f,0.f,0.f};
            #pragma unroll
            for (int kt = 0; kt < 4; ++kt) {
                mma16816(cK, A[kt], bP[kt]);
                mma16816(cV, A[kt], bG[kt]);
            }
            int e0 = nt*8 + 2*q;
            float2 cuK0 = pK0, cuK1 = pK1, cuV0 = pV0, cuV1 = pV1;
            if (nt < 15) {
                int e1 = e0 + 8;
                pK0 = *(const float2*)(gPyT + m*128  + e1);
                pK1 = *(const float2*)(gPyT + m2*128 + e1);
                pV0 = *(const float2*)(gGyT + m*128  + e1);
                pV1 = *(const float2*)(gGyT + m2*128 + e1);
            }
            float2 bk = *(const float2*)(baseK + e0);
            float2 bv = *(const float2*)(baseV + e0);
            *(unsigned*)(Ks + m *KPITCH + e0) = pk(cK[0]+bk.x-cuK0.x, cK[1]+bk.y-cuK0.y);
            *(unsigned*)(Ks + m2*KPITCH + e0) = pk(cK[2]+bk.x-cuK1.x, cK[3]+bk.y-cuK1.y);
            *(unsigned*)(Vs + m *KPITCH + e0) = pk(cV[0]+bv.x-cuV0.x, cV[1]+bv.y-cuV0.y);
            *(unsigned*)(Vs + m2*KPITCH + e0) = pk(cV[2]+bv.x-cuV1.x, cV[3]+bv.y-cuV1.y);
        }
    }
    __syncthreads();

    // ---- phase C: attention, 32 units = (head, 32-query tile); 2 per warp ----
    unsigned ksb = (unsigned)__cvta_generic_to_shared(Ks);
    unsigned vsb = (unsigned)__cvta_generic_to_shared(Vs);
    int kRow = (lane & 7) + ((lane >> 4) & 1)*8;
    int kCol = ((lane >> 3) & 1)*8;
    int vRow = (lane & 7) + ((lane >> 3) & 1)*8;
    int vCol = ((lane >> 4) & 1)*8;
    for (int u = 0; u < 2; ++u) {
        int unit = w + u*16;          // 0..31
        int hh = unit >> 3;           // head
        int qb = (unit & 7)*32;       // query tile base
        unsigned Aq[2][2][4];
        const float* Qp = gQ + hh*NQ*32;
        #pragma unroll
        for (int mt = 0; mt < 2; ++mt)
          #pragma unroll
          for (int kt = 0; kt < 2; ++kt) {
            int rA = qb + mt*16 + g, rB = rA + 8;
            int c0 = kt*16 + 2*q, c1 = c0 + 8;
            float2 f;
            f = *(const float2*)(Qp + rA*32 + c0); Aq[mt][kt][0] = pk(f.x, f.y);
            f = *(const float2*)(Qp + rB*32 + c0); Aq[mt][kt][1] = pk(f.x, f.y);
            f = *(const float2*)(Qp + rA*32 + c1); Aq[mt][kt][2] = pk(f.x, f.y);
            f = *(const float2*)(Qp + rB*32 + c1); Aq[mt][kt][3] = pk(f.x, f.y);
          }
        float O[2][4][4];
        #pragma unroll
        for (int a = 0; a < 2; ++a)
            #pragma unroll
            for (int b = 0; b < 4; ++b)
                #pragma unroll
                for (int cc = 0; cc < 4; ++cc) O[a][b][cc] = 0.f;
        float ls[2][2] = {{0.f, 0.f}, {0.f, 0.f}};
        #pragma unroll
        for (int st = 0; st < CHUNK/16; ++st) {
            int key0 = st*16;
            unsigned Bk[2][2][2];  // [ntk][kt][reg]
            unsigned ak = ksb + (unsigned)(((key0 + kRow)*KPITCH + hh*32 + kCol)*2);
            ldsm4(Bk[0][0][0], Bk[0][0][1], Bk[1][0][0], Bk[1][0][1], ak);
            ldsm4(Bk[0][1][0], Bk[0][1][1], Bk[1][1][0], Bk[1][1][1], ak + 32);
            unsigned Bv[4][2];
            unsigned av = vsb + (unsigned)(((key0 + vRow)*KPITCH + hh*32 + vCol)*2);
            ldsm4t(Bv[0][0], Bv[0][1], Bv[1][0], Bv[1][1], av);
            ldsm4t(Bv[2][0], Bv[2][1], Bv[3][0], Bv[3][1], av + 32);
            #pragma unroll
            for (int mt = 0; mt < 2; ++mt) {
                float S0[4] = {0,0,0,0}, S1[4] = {0,0,0,0};
                mma16816(S0, Aq[mt][0], Bk[0][0]);
                mma16816(S1, Aq[mt][0], Bk[1][0]);
                mma16816(S0, Aq[mt][1], Bk[0][1]);
                mma16816(S1, Aq[mt][1], Bk[1][1]);
                float p0 = ex2(S0[0]), p1 = ex2(S0[1]), p2 = ex2(S0[2]), p3 = ex2(S0[3]);
                float p4 = ex2(S1[0]), p5 = ex2(S1[1]), p6 = ex2(S1[2]), p7 = ex2(S1[3]);
                ls[mt][0] += (p0 + p1) + (p4 + p5);
                ls[mt][1] += (p2 + p3) + (p6 + p7);
                unsigned P[4] = { pk(p0, p1), pk(p2, p3), pk(p4, p5), pk(p6, p7) };
                #pragma unroll
                for (int nt = 0; nt < 4; ++nt)
                    mma16816(O[mt][nt], P, Bv[nt]);
            }
        }
        #pragma unroll
        for (int mt = 0; mt < 2; ++mt) {
            float l0 = ls[mt][0], l1 = ls[mt][1];
            l0 += __shfl_xor_sync(0xffffffffu, l0, 1);
            l0 += __shfl_xor_sync(0xffffffffu, l0, 2);
            l1 += __shfl_xor_sync(0xffffffffu, l1, 1);
            l1 += __shfl_xor_sync(0xffffffffu, l1, 2);
            int n0 = qb + mt*16 + g;
            if (q == 0) {
                gPartL[(hh*NQ + n0)*NCH + np]   = l0;
                gPartL[(hh*NQ + n0+8)*NCH + np] = l1;
            }
            #pragma unroll
            for (int nt = 0; nt < 4; ++nt) {
                float2 v;
                v.x = O[mt][nt][0]; v.y = O[mt][nt][1];
                *(float2*)(gPartO + ((size_t)(hh*NQ + n0)*NCH + np)*32 + nt*8 + 2*q) = v;
                v.x = O[mt][nt][2]; v.y = O[mt][nt][3];
                *(float2*)(gPartO + ((size_t)(hh*NQ + n0+8)*NCH + np)*32 + nt*8 + 2*q) = v;
            }
        }
    }
}

// ---------------- 6: merge partials + out-proj + residual + LayerNorm -------
__global__ void merge_kernel(const float* __restrict__ x,
                             const float* __restrict__ out_w,
                             const float* __restrict__ ln_g,
                             const float* __restrict__ ln_b,
                             float* __restrict__ out) {
    __shared__ float o_s[128];
    __shared__ float r_s[256];
    __shared__ float red[4];
    int n = blockIdx.x;
    int t = threadIdx.x;    // 128
    int h = t >> 5, d = t & 31;
    const float* po = gPartO + ((size_t)(h*NQ + n)*NCH)*32 + d;
    float acc = 0.f;
    #pragma unroll 8
    for (int c = 0; c < NCH; ++c) acc += po[c*32];
    const float* pl = gPartL + (h*NQ + n)*NCH;
    float ll = 0.f;
    for (int c = d; c < NCH; c += 32) ll += pl[c];
    #pragma unroll
    for (int o = 16; o > 0; o >>= 1) ll += __shfl_xor_sync(0xffffffffu, ll, o);
    o_s[h*32 + d] = acc / ll;
    __syncthreads();
    for (int k = 0; k < 2; ++k) {
        int dd = t + k*128;
        float a = x[n*256 + dd];
        const float4* wp = (const float4*)(out_w + dd*128);
        const float4* op = (const float4*)o_s;
        #pragma unroll 8
        for (int u = 0; u < 32; ++u) {
            float4 aa = wp[u]; float4 bb = op[u];
            a += aa.x*bb.x + aa.y*bb.y + aa.z*bb.z + aa.w*bb.w;
        }
        r_s[dd] = a;
    }
    __syncthreads();
    float s = r_s[t] + r_s[t+128];
    #pragma unroll
    for (int o = 16; o > 0; o >>= 1) s += __shfl_xor_sync(0xffffffffu, s, o);
    if ((t & 31) == 0) red[t >> 5] = s;
    __syncthreads();
    float mu = (red[0] + red[1] + red[2] + red[3]) * (1.f/256.f);
    float d0 = r_s[t] - mu, d1 = r_s[t+128] - mu;
    float sq = d0*d0 + d1*d1;
    #pragma unroll
    for (int o = 16; o > 0; o >>= 1) sq += __shfl_xor_sync(0xffffffffu, sq, o);
    __syncthreads();
    if ((t & 31) == 0) red[t >> 5] = sq;
    __syncthreads();
    float var = (red[0] + red[1] + red[2] + red[3]) * (1.f/256.f);
    float rstd = rsqrtf(var + 1e-5f);
    out[n*256 + t]       = d0*rstd*ln_g[t]     + ln_b[t];
    out[n*256 + t + 128] = d1*rstd*ln_g[t+128] + ln_b[t+128];
}

// ---------------- launcher --------------------------------------------------
extern "C" void kernel_launch(void* const* d_in, const int* in_sizes, int n_in,
                              void* d_out, int out_size) {
    const float* x       = (const float*)d_in[0];
    const float* y       = (const float*)d_in[1];
    const float* x_pos   = (const float*)d_in[2];
    const float* y_pos   = (const float*)d_in[3];
    const float* theta_w = (const float*)d_in[4];
    const float* phi_w   = (const float*)d_in[5];
    const float* g_w     = (const float*)d_in[6];
    const float* q_w1    = (const float*)d_in[7];
    const float* q_b1    = (const float*)d_in[8];
    const float* q_w2    = (const float*)d_in[9];
    const float* q_b2    = (const float*)d_in[10];
    const float* k_w1    = (const float*)d_in[11];
    const float* k_b1    = (const float*)d_in[12];
    const float* k_w2    = (const float*)d_in[13];
    const float* k_b2    = (const float*)d_in[14];
    const float* out_w   = (const float*)d_in[15];
    const float* ln_g    = (const float*)d_in[16];
    const float* ln_b    = (const float*)d_in[17];
    float* out = (float*)d_out;

    size_t smem_proj = (size_t)(128*WS_PITCH + 256) * sizeof(float);
    size_t smem_cd   = (size_t)(128*WE_PITCH + 128*64) * sizeof(float);
    cudaFuncSetAttribute(proj_kernel,  cudaFuncAttributeMaxDynamicSharedMemorySize, (int)smem_proj);
    cudaFuncSetAttribute(cd_kernel,    cudaFuncAttributeMaxDynamicSharedMemorySize, (int)smem_cd);
    cudaFuncSetAttribute(fused_kernel, cudaFuncAttributeMaxDynamicSharedMemorySize, FZ_SMEM);

    proj_kernel<<<dim3(2,2,32), 128, smem_proj>>>(x, y, phi_w, g_w);
    cd_kernel<<<16, 256, smem_cd>>>(phi_w, g_w, k_w2, k_b2);
    q_kernel<<<256, 128>>>(x, x_pos, q_w1, q_b1, q_w2, q_b2, theta_w);
    fused_kernel<<<256, 512, FZ_SMEM>>>(x_pos, y_pos, k_w1, k_b1);
    merge_kernel<<<NQ, 128>>>(x, out_w, ln_g, ln_b, out);
}

// round 9
// speedup vs baseline: 6.5734x; 1.3255x over previous
#include <cuda_runtime.h>
#include <cuda_bf16.h>
#include <math.h>

#define NQ 256
#define MM 256
#define EE 128
#define HH 4
#define PP 64
#define NK (NQ*MM)        // 65536 keys
#define CHUNK 256
#define NCH (NK/CHUNK)    // 256 chunks per head (= one np per chunk)

// ---------------- device scratch (static: no allocation allowed) ----------
__device__ float gPxT[NQ*EE];
__device__ float gPyT[MM*EE];
__device__ float gGxT[NQ*EE];
__device__ float gGyT[MM*EE];
__device__ float gQxT[NQ*EE];             // theta_x @ x^T
__device__ float gdphi[EE];
__device__ float gdg[EE];
__device__ float gdth[EE];
__device__ float gCthT[PP*EE];            // f32 [p][e]  (theta_e @ q_w2)^T
__device__ float gQ[HH*NQ*32];            // pre-scaled by 1/sqrt(32)*log2(e)
__device__ unsigned short gCphiB[EE*PP];  // bf16 [e][p]
__device__ unsigned short gCgB[EE*PP];    // bf16 [e][p]
__device__ float gPartO[(size_t)HH*NQ*NCH*32];  // 33.5 MB
__device__ float gPartL[HH*NQ*NCH];

// ---------------- mma / ldmatrix helpers ------------------------------------
__device__ __forceinline__ unsigned pk(float lo, float hi) {
    unsigned d;
    asm("cvt.rn.bf16x2.f32 %0, %1, %2;" : "=r"(d) : "f"(hi), "f"(lo));
    return d;
}
__device__ __forceinline__ float ex2(float x) {
    float d;
    asm("ex2.approx.f32 %0, %1;" : "=f"(d) : "f"(x));
    return d;
}
__device__ __forceinline__ void mma16816(float* c, const unsigned* a, const unsigned* b) {
    asm volatile(
        "mma.sync.aligned.m16n8k16.row.col.f32.bf16.bf16.f32 "
        "{%0,%1,%2,%3},{%4,%5,%6,%7},{%8,%9},{%0,%1,%2,%3};"
        : "+f"(c[0]), "+f"(c[1]), "+f"(c[2]), "+f"(c[3])
        : "r"(a[0]), "r"(a[1]), "r"(a[2]), "r"(a[3]), "r"(b[0]), "r"(b[1]));
}
__device__ __forceinline__ void ldsm4(unsigned& x, unsigned& y, unsigned& z, unsigned& w,
                                      unsigned addr) {
    asm volatile("ldmatrix.sync.aligned.m8n8.x4.shared.b16 {%0,%1,%2,%3}, [%4];"
                 : "=r"(x), "=r"(y), "=r"(z), "=r"(w) : "r"(addr));
}
__device__ __forceinline__ void ldsm4t(unsigned& x, unsigned& y, unsigned& z, unsigned& w,
                                       unsigned addr) {
    asm volatile("ldmatrix.sync.aligned.m8n8.x4.trans.shared.b16 {%0,%1,%2,%3}, [%4];"
                 : "=r"(x), "=r"(y), "=r"(z), "=r"(w) : "r"(addr));
}

// ---------------- 1: proj via bf16 mma: out = W[:, :256] @ src^T ------------
// 5 combos: (x,phi)->gPxT (y,phi)->gPyT (x,g)->gGxT (y,g)->gGyT (x,theta)->gQxT
// smem: Wb bf16 [128][264], Rb bf16 [32][264]
#define PJ_W_OFF 0
#define PJ_R_OFF 69632
#define PJ_SMEM  86528
__global__ void __launch_bounds__(256) proj_kernel(
        const float* __restrict__ x, const float* __restrict__ y,
        const float* __restrict__ phi_w, const float* __restrict__ g_w,
        const float* __restrict__ theta_w) {
    extern __shared__ char smc[];
    unsigned short* Wb = (unsigned short*)(smc + PJ_W_OFF);
    unsigned short* Rb = (unsigned short*)(smc + PJ_R_OFF);
    int combo = blockIdx.x >> 3;   // 0..4
    int rt    = blockIdx.x & 7;    // 32-row tile
    const float* w    = (combo < 2) ? phi_w : (combo < 4) ? g_w : theta_w;
    const float* srcp = (combo == 1 || combo == 3) ? y : x;
    float* outT = combo==0 ? gPxT : combo==1 ? gPyT : combo==2 ? gGxT
                : combo==3 ? gGyT : gQxT;
    int tid = threadIdx.x;  // 256
    for (int idx = tid; idx < 128*128; idx += 256) {
        int e = idx >> 7, c = idx & 127;
        float2 f = *(const float2*)(w + e*384 + c*2);
        ((unsigned*)(Wb + e*264))[c] = pk(f.x, f.y);
    }
    for (int idx = tid; idx < 32*128; idx += 256) {
        int r = idx >> 7, c = idx & 127;
        float2 f = *(const float2*)(srcp + (rt*32 + r)*256 + c*2);
        ((unsigned*)(Rb + r*264))[c] = pk(f.x, f.y);
    }
    __syncthreads();
    int wq = tid >> 5, lane = tid & 31, g = lane >> 2, q = lane & 3;
    int mtile = wq & 1;        // 16-row half
    int eg    = wq >> 1;       // 0..3, 32 e's each
    int arow = mtile*16 + (lane & 7) + ((lane >> 3) & 1)*8;
    int acol = ((lane >> 4) & 1)*8;
    unsigned rbase = (unsigned)__cvta_generic_to_shared(Rb);
    unsigned wbase = (unsigned)__cvta_generic_to_shared(Wb)
                   + (unsigned)(((eg*32 + (lane & 7))*264 + (lane >> 3)*8)*2);
    float C[4][4];
    #pragma unroll
    for (int ng = 0; ng < 4; ++ng)
        #pragma unroll
        for (int i = 0; i < 4; ++i) C[ng][i] = 0.f;
    #pragma unroll
    for (int kb = 0; kb < 8; ++kb) {   // 32 k per step
        unsigned A0[4], A1[4];
        unsigned abase = rbase + (unsigned)((arow*264 + kb*32 + acol)*2);
        ldsm4(A0[0], A0[1], A0[2], A0[3], abase);
        ldsm4(A1[0], A1[1], A1[2], A1[3], abase + 32);
        #pragma unroll
        for (int ng = 0; ng < 4; ++ng) {
            unsigned b[4];
            ldsm4(b[0], b[1], b[2], b[3], wbase + (unsigned)((ng*8*264 + kb*32)*2));
            mma16816(C[ng], A0, b);
            mma16816(C[ng], A1, b + 2);
        }
    }
    int row = rt*32 + mtile*16 + g;
    #pragma unroll
    for (int ng = 0; ng < 4; ++ng) {
        int e = eg*32 + ng*8 + 2*q;
        float2 v0; v0.x = C[ng][0]; v0.y = C[ng][1];
        float2 v1; v1.x = C[ng][2]; v1.y = C[ng][3];
        *(float2*)(outT + row*128 + e)     = v0;
        *(float2*)(outT + (row+8)*128 + e) = v1;
    }
}

// ---------------- 2: C = W[:,256:] @ w2,  d = W[:,256:] @ b2 ----------------
// wi 0: phi@k_w2 -> gCphiB(bf16), gdphi;  1: g@k_w2 -> gCgB, gdg;
// wi 2: theta@q_w2 -> gCthT(f32, [p][e]), gdth
#define WE_PITCH 129
__global__ void cd_kernel(const float* __restrict__ phi_w,
                          const float* __restrict__ g_w,
                          const float* __restrict__ theta_w,
                          const float* __restrict__ k_w2,
                          const float* __restrict__ k_b2,
                          const float* __restrict__ q_w2,
                          const float* __restrict__ q_b2) {
    extern __shared__ float sm[];
    float* we  = sm;                    // 128 x 129
    float* kw2 = sm + 128*WE_PITCH;     // 128 x 64
    int wi = blockIdx.x % 3;
    int pg = blockIdx.x / 3;            // 0..7, 8 p's per block
    const float* w   = wi==0 ? phi_w : wi==1 ? g_w : theta_w;
    const float* w2  = wi==2 ? q_w2 : k_w2;
    const float* b2  = wi==2 ? q_b2 : k_b2;
    unsigned short* CtB = wi==1 ? gCgB : gCphiB;
    float* dv  = wi==0 ? gdphi : wi==1 ? gdg : gdth;
    int tid = threadIdx.x;              // 256
    for (int idx = tid; idx < 128*128; idx += 256) {
        int e = idx >> 7, c = idx & 127;
        we[e*WE_PITCH + c] = w[e*384 + 256 + c];
    }
    for (int idx = tid; idx < 128*64; idx += 256) kw2[idx] = w2[idx];
    __syncthreads();
    int e  = tid & 127;
    int ph = tid >> 7;  // 0..1
    if (pg == 0 && ph == 0) {
        float acc = 0.f;
        for (int c = 0; c < 128; ++c) acc += we[e*WE_PITCH + c]*b2[c];
        dv[e] = acc;
    }
    for (int j = 0; j < 4; ++j) {
        int p = pg*8 + ph*4 + j;
        float acc = 0.f;
        #pragma unroll 8
        for (int c = 0; c < 128; ++c)
            acc += we[e*WE_PITCH + c] * kw2[c*64 + p];
        if (wi == 2) {
            gCthT[p*128 + e] = acc;
        } else {
            __nv_bfloat16 b = __float2bfloat16(acc);
            CtB[e*64 + p] = *(unsigned short*)&b;
        }
    }
}

// ---------------- 3: Q = scale * (Qx + Cth^T hid + dth) ---------------------
__global__ void q_kernel(const float* __restrict__ x_pos,
                         const float* __restrict__ q_w1,
                         const float* __restrict__ q_b1) {
    __shared__ float hid[64];
    int n = blockIdx.x;
    int t = threadIdx.x;   // 128
    if (t < 64) {
        float r0 = x_pos[n*3], r1 = x_pos[n*3+1], r2 = x_pos[n*3+2];
        float h = q_w1[t*3]*r0 + q_w1[t*3+1]*r1 + q_w1[t*3+2]*r2 + q_b1[t];
        hid[t] = fmaxf(h, 0.f);
    }
    __syncthreads();
    int e = t;
    float a0 = 0.f, a1 = 0.f;
    #pragma unroll
    for (int p = 0; p < 64; p += 2) {
        a0 += gCthT[p*128 + e]     * hid[p];
        a1 += gCthT[(p+1)*128 + e] * hid[p+1];
    }
    float acc = gQxT[n*128 + e] + a0 + a1 + gdth[e];
    acc *= 0.17677669529663687f * 1.4426950408889634f;  // 1/sqrt(32)*log2(e)
    int h = e >> 5, d = e & 31;
    gQ[(h*NQ + n)*32 + d] = acc;
}

// ---------------- 4: FUSED genkv + flash attention --------------------------
#define KPITCH 136
#define FZ_KS_OFF 0
#define FZ_VS_OFF 69632
#define FZ_H_OFF  139264
#define FZ_CP_OFF 176128
#define FZ_CG_OFF 194560
#define FZ_BK_OFF 212992
#define FZ_BV_OFF 213504
#define FZ_YP_OFF 214016
#define FZ_SMEM   217088

__global__ void __launch_bounds__(512, 1) fused_kernel(
        const float* __restrict__ x_pos, const float* __restrict__ y_pos,
        const float* __restrict__ k_w1, const float* __restrict__ k_b1) {
    extern __shared__ char smc[];
    unsigned short* Ks = (unsigned short*)(smc + FZ_KS_OFF);  // [256][136] bf16
    unsigned short* Vs = (unsigned short*)(smc + FZ_VS_OFF);  // [256][136] bf16
    unsigned short* Hs = (unsigned short*)(smc + FZ_H_OFF);   // [256][72]  bf16
    float* baseK = (float*)(smc + FZ_BK_OFF);
    float* baseV = (float*)(smc + FZ_BV_OFF);
    float* yps   = (float*)(smc + FZ_YP_OFF);                 // [256][3]
    __shared__ float kw1s[192], kb1s[64];
    int tid = threadIdx.x;   // 512
    int np  = blockIdx.x;    // 0..255

    // ---- phase A: stage constants + hidden MLP ----
    for (int i = tid; i < 128*32; i += 512) {
        int e = i >> 5, c = i & 31;
        ((unsigned*)(smc + FZ_CP_OFF + e*144))[c] = ((const unsigned*)gCphiB)[e*32 + c];
        ((unsigned*)(smc + FZ_CG_OFF + e*144))[c] = ((const unsigned*)gCgB)[e*32 + c];
    }
    if (tid < 128) {
        baseK[tid] = gPxT[np*128 + tid] + gdphi[tid];
        baseV[tid] = gGxT[np*128 + tid] + gdg[tid];
    }
    for (int i = tid; i < 768; i += 512) yps[i] = y_pos[i];
    if (tid < 192) kw1s[tid] = k_w1[tid];
    if (tid >= 256 && tid < 320) kb1s[tid-256] = k_b1[tid-256];
    __syncthreads();
    float xp0 = x_pos[np*3], xp1 = x_pos[np*3+1], xp2 = x_pos[np*3+2];
    for (int i = tid; i < 256*64; i += 512) {
        int pr = i >> 6, p = i & 63;
        float r0 = xp0 - yps[pr*3], r1 = xp1 - yps[pr*3+1], r2 = xp2 - yps[pr*3+2];
        float h = fmaxf(kw1s[p*3]*r0 + kw1s[p*3+1]*r1 + kw1s[p*3+2]*r2 + kb1s[p], 0.f);
        __nv_bfloat16 hb = __float2bfloat16(h);
        Hs[pr*72 + p] = *(unsigned short*)&hb;
    }
    __syncthreads();

    int w = tid >> 5, lane = tid & 31, g = lane >> 2, q = lane & 3;

    // ---- phase B: K/V = H@C + base - Py/Gy  -> SMEM (16 warps x 16 rows) ----
    {
        int r0 = w*16;
        unsigned A[4][4];
        int arow = r0 + (lane & 7) + ((lane >> 3) & 1)*8;
        int acol = ((lane >> 4) & 1)*8;
        unsigned hbase = (unsigned)__cvta_generic_to_shared(Hs);
        #pragma unroll
        for (int kt = 0; kt < 4; ++kt)
            ldsm4(A[kt][0], A[kt][1], A[kt][2], A[kt][3],
                  hbase + (unsigned)((arow*72 + kt*16 + acol)*2));
        unsigned cpb = (unsigned)__cvta_generic_to_shared(smc + FZ_CP_OFF)
                     + (unsigned)(((lane & 7)*72 + (lane >> 3)*8)*2);
        unsigned cgb = (unsigned)__cvta_generic_to_shared(smc + FZ_CG_OFF)
                     + (unsigned)(((lane & 7)*72 + (lane >> 3)*8)*2);
        int m  = r0 + g;
        int m2 = m + 8;
        // prefetch Py/Gy for nt=0
        float2 pK0 = *(const float2*)(gPyT + m*128  + 2*q);
        float2 pK1 = *(const float2*)(gPyT + m2*128 + 2*q);
        float2 pV0 = *(const float2*)(gGyT + m*128  + 2*q);
        float2 pV1 = *(const float2*)(gGyT + m2*128 + 2*q);
        // preload B-frags for nt=0
        unsigned bP[4][2], bG[4][2];
        ldsm4(bP[0][0], bP[0][1], bP[1][0], bP[1][1], cpb);
        ldsm4(bP[2][0], bP[2][1], bP[3][0], bP[3][1], cpb + 64);
        ldsm4(bG[0][0], bG[0][1], bG[1][0], bG[1][1], cgb);
        ldsm4(bG[2][0], bG[2][1], bG[3][0], bG[3][1], cgb + 64);
        #pragma unroll
        for (int nt = 0; nt < 16; ++nt) {
            unsigned nP[4][2], nG[4][2];
            if (nt < 15) {
                unsigned offn = (unsigned)((nt+1)*8*72*2);
                ldsm4(nP[0][0], nP[0][1], nP[1][0], nP[1][1], cpb + offn);
                ldsm4(nP[2][0], nP[2][1], nP[3][0], nP[3][1], cpb + offn + 64);
                ldsm4(nG[0][0], nG[0][1], nG[1][0], nG[1][1], cgb + offn);
                ldsm4(nG[2][0], nG[2][1], nG[3][0], nG[3][1], cgb + offn + 64);
            }
            float cK[4] = {0.f,0.f,0.f,0.f}, cV[4] = {0.f,0.f,0.f,0.f};
            #pragma unroll
            for (int kt = 0; kt < 4; ++kt) {
                mma16816(cK, A[kt], bP[kt]);
                mma16816(cV, A[kt], bG[kt]);
            }
            int e0 = nt*8 + 2*q;
            float2 cuK0 = pK0, cuK1 = pK1, cuV0 = pV0, cuV1 = pV1;
            if (nt < 15) {
                int e1 = e0 + 8;
                pK0 = *(const float2*)(gPyT + m*128  + e1);
                pK1 = *(const float2*)(gPyT + m2*128 + e1);
                pV0 = *(const float2*)(gGyT + m*128  + e1);
                pV1 = *(const float2*)(gGyT + m2*128 + e1);
            }
            float2 bk = *(const float2*)(baseK + e0);
            float2 bv = *(const float2*)(baseV + e0);
            *(unsigned*)(Ks + m *KPITCH + e0) = pk(cK[0]+bk.x-cuK0.x, cK[1]+bk.y-cuK0.y);
            *(unsigned*)(Ks + m2*KPITCH + e0) = pk(cK[2]+bk.x-cuK1.x, cK[3]+bk.y-cuK1.y);
            *(unsigned*)(Vs + m *KPITCH + e0) = pk(cV[0]+bv.x-cuV0.x, cV[1]+bv.y-cuV0.y);
            *(unsigned*)(Vs + m2*KPITCH + e0) = pk(cV[2]+bv.x-cuV1.x, cV[3]+bv.y-cuV1.y);
            if (nt < 15) {
                #pragma unroll
                for (int i = 0; i < 4; ++i) {
                    bP[i][0] = nP[i][0]; bP[i][1] = nP[i][1];
                    bG[i][0] = nG[i][0]; bG[i][1] = nG[i][1];
                }
            }
        }
    }
    __syncthreads();

    // ---- phase C: attention, 32 units = (head, 32-query tile); 2 per warp ----
    unsigned ksb = (unsigned)__cvta_generic_to_shared(Ks);
    unsigned vsb = (unsigned)__cvta_generic_to_shared(Vs);
    int kRow = (lane & 7) + ((lane >> 4) & 1)*8;
    int kCol = ((lane >> 3) & 1)*8;
    int vRow = (lane & 7) + ((lane >> 3) & 1)*8;
    int vCol = ((lane >> 4) & 1)*8;
    for (int u = 0; u < 2; ++u) {
        int unit = w + u*16;          // 0..31
        int hh = unit >> 3;           // head
        int qb = (unit & 7)*32;       // query tile base
        unsigned Aq[2][2][4];
        const float* Qp = gQ + hh*NQ*32;
        #pragma unroll
        for (int mt = 0; mt < 2; ++mt)
          #pragma unroll
          for (int kt = 0; kt < 2; ++kt) {
            int rA = qb + mt*16 + g, rB = rA + 8;
            int c0 = kt*16 + 2*q, c1 = c0 + 8;
            float2 f;
            f = *(const float2*)(Qp + rA*32 + c0); Aq[mt][kt][0] = pk(f.x, f.y);
            f = *(const float2*)(Qp + rB*32 + c0); Aq[mt][kt][1] = pk(f.x, f.y);
            f = *(const float2*)(Qp + rA*32 + c1); Aq[mt][kt][2] = pk(f.x, f.y);
            f = *(const float2*)(Qp + rB*32 + c1); Aq[mt][kt][3] = pk(f.x, f.y);
          }
        float O[2][4][4];
        #pragma unroll
        for (int a = 0; a < 2; ++a)
            #pragma unroll
            for (int b = 0; b < 4; ++b)
                #pragma unroll
                for (int cc = 0; cc < 4; ++cc) O[a][b][cc] = 0.f;
        float ls[2][2] = {{0.f, 0.f}, {0.f, 0.f}};
        unsigned ak0 = ksb + (unsigned)((kRow*KPITCH + hh*32 + kCol)*2);
        unsigned av0 = vsb + (unsigned)((vRow*KPITCH + hh*32 + vCol)*2);
        // preload subtile 0
        unsigned Bk[2][2][2], Bv[4][2];
        ldsm4(Bk[0][0][0], Bk[0][0][1], Bk[1][0][0], Bk[1][0][1], ak0);
        ldsm4(Bk[0][1][0], Bk[0][1][1], Bk[1][1][0], Bk[1][1][1], ak0 + 32);
        ldsm4t(Bv[0][0], Bv[0][1], Bv[1][0], Bv[1][1], av0);
        ldsm4t(Bv[2][0], Bv[2][1], Bv[3][0], Bv[3][1], av0 + 32);
        #pragma unroll
        for (int st = 0; st < CHUNK/16; ++st) {
            unsigned nBk[2][2][2], nBv[4][2];
            if (st < CHUNK/16 - 1) {
                unsigned ak = ak0 + (unsigned)((st+1)*16*KPITCH*2);
                unsigned av = av0 + (unsigned)((st+1)*16*KPITCH*2);
                ldsm4(nBk[0][0][0], nBk[0][0][1], nBk[1][0][0], nBk[1][0][1], ak);
                ldsm4(nBk[0][1][0], nBk[0][1][1], nBk[1][1][0], nBk[1][1][1], ak + 32);
                ldsm4t(nBv[0][0], nBv[0][1], nBv[1][0], nBv[1][1], av);
                ldsm4t(nBv[2][0], nBv[2][1], nBv[3][0], nBv[3][1], av + 32);
            }
            #pragma unroll
            for (int mt = 0; mt < 2; ++mt) {
                float S0[4] = {0,0,0,0}, S1[4] = {0,0,0,0};
                mma16816(S0, Aq[mt][0], Bk[0][0]);
                mma16816(S1, Aq[mt][0], Bk[1][0]);
                mma16816(S0, Aq[mt][1], Bk[0][1]);
                mma16816(S1, Aq[mt][1], Bk[1][1]);
                float p0 = ex2(S0[0]), p1 = ex2(S0[1]), p2 = ex2(S0[2]), p3 = ex2(S0[3]);
                float p4 = ex2(S1[0]), p5 = ex2(S1[1]), p6 = ex2(S1[2]), p7 = ex2(S1[3]);
                ls[mt][0] += (p0 + p1) + (p4 + p5);
                ls[mt][1] += (p2 + p3) + (p6 + p7);
                unsigned P[4] = { pk(p0, p1), pk(p2, p3), pk(p4, p5), pk(p6, p7) };
                #pragma unroll
                for (int nt = 0; nt < 4; ++nt)
                    mma16816(O[mt][nt], P, Bv[nt]);
            }
            if (st < CHUNK/16 - 1) {
                #pragma unroll
                for (int i = 0; i < 2; ++i)
                    #pragma unroll
                    for (int j = 0; j < 2; ++j) {
                        Bk[i][j][0] = nBk[i][j][0]; Bk[i][j][1] = nBk[i][j][1];
                    }
                #pragma unroll
                for (int i = 0; i < 4; ++i) {
                    Bv[i][0] = nBv[i][0]; Bv[i][1] = nBv[i][1];
                }
            }
        }
        #pragma unroll
        for (int mt = 0; mt < 2; ++mt) {
            float l0 = ls[mt][0], l1 = ls[mt][1];
            l0 += __shfl_xor_sync(0xffffffffu, l0, 1);
            l0 += __shfl_xor_sync(0xffffffffu, l0, 2);
            l1 += __shfl_xor_sync(0xffffffffu, l1, 1);
            l1 += __shfl_xor_sync(0xffffffffu, l1, 2);
            int n0 = qb + mt*16 + g;
            if (q == 0) {
                gPartL[(hh*NQ + n0)*NCH + np]   = l0;
                gPartL[(hh*NQ + n0+8)*NCH + np] = l1;
            }
            #pragma unroll
            for (int nt = 0; nt < 4; ++nt) {
                float2 v;
                v.x = O[mt][nt][0]; v.y = O[mt][nt][1];
                *(float2*)(gPartO + ((size_t)(hh*NQ + n0)*NCH + np)*32 + nt*8 + 2*q) = v;
                v.x = O[mt][nt][2]; v.y = O[mt][nt][3];
                *(float2*)(gPartO + ((size_t)(hh*NQ + n0+8)*NCH + np)*32 + nt*8 + 2*q) = v;
            }
        }
    }
}

// ---------------- 6: merge partials + out-proj + residual + LayerNorm -------
__global__ void merge_kernel(const float* __restrict__ x,
                             const float* __restrict__ out_w,
                             const float* __restrict__ ln_g,
                             const float* __restrict__ ln_b,
                             float* __restrict__ out) {
    __shared__ float o_s[128];
    __shared__ float r_s[256];
    __shared__ float red[4];
    int n = blockIdx.x;
    int t = threadIdx.x;    // 128
    int h = t >> 5, d = t & 31;
    const float* po = gPartO + ((size_t)(h*NQ + n)*NCH)*32 + d;
    float a0 = 0.f, a1 = 0.f, a2 = 0.f, a3 = 0.f;
    #pragma unroll 4
    for (int c = 0; c < NCH; c += 4) {
        a0 += po[(c+0)*32];
        a1 += po[(c+1)*32];
        a2 += po[(c+2)*32];
        a3 += po[(c+3)*32];
    }
    float acc = (a0 + a1) + (a2 + a3);
    const float* pl = gPartL + (h*NQ + n)*NCH;
    float ll = 0.f;
    for (int c = d; c < NCH; c += 32) ll += pl[c];
    #pragma unroll
    for (int o = 16; o > 0; o >>= 1) ll += __shfl_xor_sync(0xffffffffu, ll, o);
    o_s[h*32 + d] = acc / ll;
    __syncthreads();
    for (int k = 0; k < 2; ++k) {
        int dd = t + k*128;
        float a = x[n*256 + dd];
        const float4* wp = (const float4*)(out_w + dd*128);
        const float4* op = (const float4*)o_s;
        #pragma unroll 8
        for (int u = 0; u < 32; ++u) {
            float4 aa = wp[u]; float4 bb = op[u];
            a += aa.x*bb.x + aa.y*bb.y + aa.z*bb.z + aa.w*bb.w;
        }
        r_s[dd] = a;
    }
    __syncthreads();
    float s = r_s[t] + r_s[t+128];
    #pragma unroll
    for (int o = 16; o > 0; o >>= 1) s += __shfl_xor_sync(0xffffffffu, s, o);
    if ((t & 31) == 0) red[t >> 5] = s;
    __syncthreads();
    float mu = (red[0] + red[1] + red[2] + red[3]) * (1.f/256.f);
    float d0 = r_s[t] - mu, d1 = r_s[t+128] - mu;
    float sq = d0*d0 + d1*d1;
    #pragma unroll
    for (int o = 16; o > 0; o >>= 1) sq += __shfl_xor_sync(0xffffffffu, sq, o);
    __syncthreads();
    if ((t & 31) == 0) red[t >> 5] = sq;
    __syncthreads();
    float var = (red[0] + red[1] + red[2] + red[3]) * (1.f/256.f);
    float rstd = rsqrtf(var + 1e-5f);
    out[n*256 + t]       = d0*rstd*ln_g[t]     + ln_b[t];
    out[n*256 + t + 128] = d1*rstd*ln_g[t+128] + ln_b[t+128];
}

// ---------------- launcher --------------------------------------------------
extern "C" void kernel_launch(void* const* d_in, const int* in_sizes, int n_in,
                              void* d_out, int out_size) {
    const float* x       = (const float*)d_in[0];
    const float* y       = (const float*)d_in[1];
    const float* x_pos   = (const float*)d_in[2];
    const float* y_pos   = (const float*)d_in[3];
    const float* theta_w = (const float*)d_in[4];
    const float* phi_w   = (const float*)d_in[5];
    const float* g_w     = (const float*)d_in[6];
    const float* q_w1    = (const float*)d_in[7];
    const float* q_b1    = (const float*)d_in[8];
    const float* q_w2    = (const float*)d_in[9];
    const float* q_b2    = (const float*)d_in[10];
    const float* k_w1    = (const float*)d_in[11];
    const float* k_b1    = (const float*)d_in[12];
    const float* k_w2    = (const float*)d_in[13];
    const float* k_b2    = (const float*)d_in[14];
    const float* out_w   = (const float*)d_in[15];
    const float* ln_g    = (const float*)d_in[16];
    const float* ln_b    = (const float*)d_in[17];
    float* out = (float*)d_out;

    size_t smem_cd = (size_t)(128*WE_PITCH + 128*64) * sizeof(float);
    cudaFuncSetAttribute(proj_kernel,  cudaFuncAttributeMaxDynamicSharedMemorySize, PJ_SMEM);
    cudaFuncSetAttribute(cd_kernel,    cudaFuncAttributeMaxDynamicSharedMemorySize, (int)smem_cd);
    cudaFuncSetAttribute(fused_kernel, cudaFuncAttributeMaxDynamicSharedMemorySize, FZ_SMEM);

    proj_kernel<<<40, 256, PJ_SMEM>>>(x, y, phi_w, g_w, theta_w);
    cd_kernel<<<24, 256, smem_cd>>>(phi_w, g_w, theta_w, k_w2, k_b2, q_w2, q_b2);
    q_kernel<<<256, 128>>>(x_pos, q_w1, q_b1);
    fused_kernel<<<256, 512, FZ_SMEM>>>(x_pos, y_pos, k_w1, k_b1);
    merge_kernel<<<NQ, 128>>>(x, out_w, ln_g, ln_b, out);
}